// round 11
// baseline (speedup 1.0000x reference)
#include <cuda_runtime.h>
#include <cuda_bf16.h>
#include <mma.h>
#include <cstdint>

using namespace nvcuda;
typedef __nv_bfloat16 bf16;

#define Bsz 8192
#define Tn  12
#define DIN 64
#define HID 512
#define ENCD 128
#define Rr  64

// ================= device-global scratch =================
__device__ __align__(256) float   g_encf[Tn * Bsz * ENCD];          // fp32 enc [t][b][e]
__device__ __align__(256) int8_t  g_A8h[Tn * Bsz * ENCD];
__device__ __align__(256) int8_t  g_A8l[Tn * Bsz * ENCD];
__device__ __align__(256) float   g_sa[Tn * Bsz];
__device__ __align__(256) int8_t  g_B8h[(Tn - 2) * Rr * Rr * ENCD]; // [t][n=r*64+p][e]
__device__ __align__(256) int8_t  g_B8l[(Tn - 2) * Rr * Rr * ENCD];
__device__ __align__(256) float   g_sb[(Tn - 2) * Rr * Rr];
__device__ __align__(256) bf16    g_W1hi[HID * DIN],  g_W1lo[HID * DIN];
__device__ __align__(256) bf16    g_W2hi[ENCD * HID], g_W2lo[ENCD * HID];

__device__ __forceinline__ uint32_t smem_u32(const void* p) {
    uint32_t a;
    asm("{ .reg .u64 t; cvta.to.shared.u64 t, %1; cvt.u32.u64 %0, t; }" : "=r"(a) : "l"(p));
    return a;
}
__device__ __forceinline__ void cp16(uint32_t dst, const void* src) {
    asm volatile("cp.async.cg.shared.global [%0], [%1], 16;" :: "r"(dst), "l"(src));
}
#define CP_COMMIT()  asm volatile("cp.async.commit_group;")
#define CP_WAIT(N)   asm volatile("cp.async.wait_group %0;" :: "n"(N))

__device__ __forceinline__ void ldmx4(uint32_t* r, uint32_t a) {
    asm volatile("ldmatrix.sync.aligned.m8n8.x4.shared.b16 {%0,%1,%2,%3}, [%4];"
                 : "=r"(r[0]), "=r"(r[1]), "=r"(r[2]), "=r"(r[3]) : "r"(a));
}
__device__ __forceinline__ void imma(int* d, const uint32_t* a, const uint32_t* b) {
    asm volatile("mma.sync.aligned.m16n8k32.row.col.s32.s8.s8.s32 "
                 "{%0,%1,%2,%3}, {%4,%5,%6,%7}, {%8,%9}, {%0,%1,%2,%3};"
                 : "+r"(d[0]), "+r"(d[1]), "+r"(d[2]), "+r"(d[3])
                 : "r"(a[0]), "r"(a[1]), "r"(a[2]), "r"(a[3]), "r"(b[0]), "r"(b[1]));
}

// ================= prep: W splits =================
__global__ void prep_w_kernel(const float* __restrict__ W1,
                              const float* __restrict__ W2) {
    const int n1 = HID * DIN, n2 = ENCD * HID;
    for (int i = blockIdx.x * blockDim.x + threadIdx.x; i < n1 + n2;
         i += gridDim.x * blockDim.x) {
        const float* s; bf16 *h, *l; int j;
        if (i < n1) { s = W1; h = g_W1hi; l = g_W1lo; j = i; }
        else        { s = W2; h = g_W2hi; l = g_W2lo; j = i - n1; }
        float v = s[j];
        bf16 hi = __float2bfloat16(v);
        h[j] = hi;
        l[j] = __float2bfloat16(v - __bfloat162float(hi));
    }
}

// ================= prep: Hm[t,p,e,r] -> int8x2 [t][n=r*64+p][e] + per-col scale =================
__global__ __launch_bounds__(256) void prep_hb8_kernel(const float* __restrict__ Hm) {
    __shared__ float tile[128][65];     // [e][r]
    __shared__ float rinv[64];
    const int t = blockIdx.x >> 6, p = blockIdx.x & 63;
    const int tid = threadIdx.x;
    const float* src = Hm + ((size_t)(t * 64 + p) * 128) * 64;
    for (int i = tid; i < 128 * 64; i += 256) tile[i >> 6][i & 63] = src[i];
    __syncthreads();
    if (tid < 64) {
        float m = 0.f;
        for (int e = 0; e < 128; e++) m = fmaxf(m, fabsf(tile[e][tid]));
        g_sb[(size_t)t * 4096 + tid * 64 + p] = m / 127.f;
        rinv[tid] = (m > 0.f) ? (127.f / m) : 0.f;
    }
    __syncthreads();
    for (int i = tid; i < 64 * 128; i += 256) {
        int r = i >> 7, e = i & 127;
        float q = tile[e][r] * rinv[r];
        float h = rintf(q);
        float l = rintf((q - h) * 128.f);
        size_t a = ((size_t)t * 4096 + r * 64 + p) * 128 + e;
        g_B8h[a] = (int8_t)(int)h;
        g_B8l[a] = (int8_t)(int)l;
    }
}

// ================= encoder (R8 256-thread, fp32 out) =================
#define EX_H 0u
#define EX_L (EX_H + 64u * 72u * 2u)
#define EH_H (EX_L + 64u * 72u * 2u)
#define EH_L (EH_H + 64u * 520u * 2u)
#define E_ST (EH_L + 64u * 520u * 2u)
#define ENC2_SMEM (E_ST + 8u * 320u * 4u)

__global__ __launch_bounds__(256, 1) void encoder2_kernel(const float* __restrict__ x,
                                                          const float* __restrict__ b1,
                                                          const float* __restrict__ b2) {
    extern __shared__ char smem[];
    bf16* xs_hi = (bf16*)(smem + EX_H);
    bf16* xs_lo = (bf16*)(smem + EX_L);
    bf16* hs_hi = (bf16*)(smem + EH_H);
    bf16* hs_lo = (bf16*)(smem + EH_L);
    float* stg_base = (float*)(smem + E_ST);

    const int tid = threadIdx.x, w = tid >> 5, lane = tid & 31;
    const int wy = w >> 2, wx = w & 3;
    const int n0 = blockIdx.x * 64;
    float* stg = stg_base + w * 320;
    const int frow = lane >> 1, fcol = (lane & 1) * 8;

    #pragma unroll
    for (int k = 0; k < 16; k++) {
        int idx = tid + k * 256;
        int r = idx >> 6, c = idx & 63;
        float v = x[(size_t)(n0 + r) * DIN + c];
        bf16 hi = __float2bfloat16(v);
        xs_hi[r * 72 + c] = hi;
        xs_lo[r * 72 + c] = __float2bfloat16(v - __bfloat162float(hi));
    }
    __syncthreads();

    #pragma unroll
    for (int pass = 0; pass < 2; pass++) {
        const int cb = wx * 128 + pass * 64;
        wmma::fragment<wmma::accumulator, 16, 16, 16, float> acc[2][4];
        #pragma unroll
        for (int rf = 0; rf < 2; rf++)
            #pragma unroll
            for (int j = 0; j < 4; j++) wmma::fill_fragment(acc[rf][j], 0.0f);
        #pragma unroll
        for (int kk = 0; kk < 4; kk++) {
            wmma::fragment<wmma::matrix_a, 16, 16, 16, bf16, wmma::row_major> ahi[2], alo[2];
            #pragma unroll
            for (int rf = 0; rf < 2; rf++) {
                wmma::load_matrix_sync(ahi[rf], xs_hi + (wy * 32 + rf * 16) * 72 + kk * 16, 72);
                wmma::load_matrix_sync(alo[rf], xs_lo + (wy * 32 + rf * 16) * 72 + kk * 16, 72);
            }
            #pragma unroll
            for (int j = 0; j < 4; j++) {
                wmma::fragment<wmma::matrix_b, 16, 16, 16, bf16, wmma::col_major> bhi, blo;
                wmma::load_matrix_sync(bhi, g_W1hi + (cb + j * 16) * DIN + kk * 16, DIN);
                wmma::load_matrix_sync(blo, g_W1lo + (cb + j * 16) * DIN + kk * 16, DIN);
                #pragma unroll
                for (int rf = 0; rf < 2; rf++) {
                    wmma::mma_sync(acc[rf][j], ahi[rf], bhi, acc[rf][j]);
                    wmma::mma_sync(acc[rf][j], alo[rf], bhi, acc[rf][j]);
                    wmma::mma_sync(acc[rf][j], ahi[rf], blo, acc[rf][j]);
                }
            }
        }
        #pragma unroll
        for (int rf = 0; rf < 2; rf++)
            #pragma unroll
            for (int j = 0; j < 4; j++) {
                wmma::store_matrix_sync(stg, acc[rf][j], 20, wmma::mem_row_major);
                __syncwarp();
                const int rbase = wy * 32 + rf * 16 + frow;
                #pragma unroll
                for (int cc = 0; cc < 8; cc++) {
                    int gc = cb + j * 16 + fcol + cc;
                    float v = fmaxf(stg[frow * 20 + fcol + cc] + b1[gc], 0.0f);
                    bf16 hi = __float2bfloat16(v);
                    hs_hi[rbase * 520 + gc] = hi;
                    hs_lo[rbase * 520 + gc] = __float2bfloat16(v - __bfloat162float(hi));
                }
                __syncwarp();
            }
    }
    __syncthreads();

    {
        wmma::fragment<wmma::accumulator, 16, 16, 16, float> acc[2][2];
        #pragma unroll
        for (int rf = 0; rf < 2; rf++)
            #pragma unroll
            for (int j = 0; j < 2; j++) wmma::fill_fragment(acc[rf][j], 0.0f);
        #pragma unroll 8
        for (int kk = 0; kk < 32; kk++) {
            wmma::fragment<wmma::matrix_a, 16, 16, 16, bf16, wmma::row_major> ahi[2], alo[2];
            #pragma unroll
            for (int rf = 0; rf < 2; rf++) {
                wmma::load_matrix_sync(ahi[rf], hs_hi + (wy * 32 + rf * 16) * 520 + kk * 16, 520);
                wmma::load_matrix_sync(alo[rf], hs_lo + (wy * 32 + rf * 16) * 520 + kk * 16, 520);
            }
            #pragma unroll
            for (int j = 0; j < 2; j++) {
                wmma::fragment<wmma::matrix_b, 16, 16, 16, bf16, wmma::col_major> bhi, blo;
                wmma::load_matrix_sync(bhi, g_W2hi + (wx * 32 + j * 16) * HID + kk * 16, HID);
                wmma::load_matrix_sync(blo, g_W2lo + (wx * 32 + j * 16) * HID + kk * 16, HID);
                #pragma unroll
                for (int rf = 0; rf < 2; rf++) {
                    wmma::mma_sync(acc[rf][j], ahi[rf], bhi, acc[rf][j]);
                    wmma::mma_sync(acc[rf][j], alo[rf], bhi, acc[rf][j]);
                    wmma::mma_sync(acc[rf][j], ahi[rf], blo, acc[rf][j]);
                }
            }
        }
        #pragma unroll
        for (int rf = 0; rf < 2; rf++)
            #pragma unroll
            for (int j = 0; j < 2; j++) {
                wmma::store_matrix_sync(stg, acc[rf][j], 20, wmma::mem_row_major);
                __syncwarp();
                const int n = n0 + wy * 32 + rf * 16 + frow;
                const int b = n / Tn, tt = n % Tn;
                #pragma unroll
                for (int cc = 0; cc < 8; cc++) {
                    int e = wx * 32 + j * 16 + fcol + cc;
                    g_encf[(size_t)(tt * Bsz + b) * ENCD + e] =
                        fmaxf(stg[frow * 20 + fcol + cc] + b2[e], 0.0f);
                }
                __syncwarp();
            }
    }
}

// ================= quantize enc rows (warp per row) =================
__global__ __launch_bounds__(256) void quant_enc_kernel() {
    const int row = blockIdx.x * 8 + (threadIdx.x >> 5);
    const int lane = threadIdx.x & 31;
    float4 xv = ((const float4*)(g_encf + (size_t)row * ENCD))[lane];
    float m = fmaxf(fmaxf(xv.x, xv.y), fmaxf(xv.z, xv.w));       // enc >= 0
    #pragma unroll
    for (int off = 16; off > 0; off >>= 1)
        m = fmaxf(m, __shfl_xor_sync(0xffffffffu, m, off));
    float inv = (m > 0.f) ? (127.f / m) : 0.f;
    float vals[4] = {xv.x, xv.y, xv.z, xv.w};
    uint32_t hp = 0, lp = 0;
    #pragma unroll
    for (int c = 0; c < 4; c++) {
        float q = vals[c] * inv;
        float h = rintf(q);
        float l = rintf((q - h) * 128.f);
        hp |= ((uint32_t)((int)h & 255)) << (c * 8);
        lp |= ((uint32_t)((int)l & 255)) << (c * 8);
    }
    ((uint32_t*)(g_A8h + (size_t)row * ENCD))[lane] = hp;
    ((uint32_t*)(g_A8l + (size_t)row * ENCD))[lane] = lp;
    if (lane == 0) g_sa[row] = m / 127.f;
}

// ================= fused chain: int8x2 IMMA, 512 threads =================
#define I_AH 0u
#define I_AL (I_AH + 64u * 144u)          // 9216
#define I_SA (I_AL + 64u * 144u)          // 18432
#define I_V  (I_SA + 256u)                // 18688
#define I_B  (I_V + 2u * 64u * 72u * 4u)  // 55552
#define B8_STG 24576u                     // 256n * 48B, hi+lo (12288 each)
#define CHI_SMEM (I_B + 4u * B8_STG)      // 153856 B

__global__ __launch_bounds__(512, 1) void chain_i8_kernel(const float* __restrict__ Hf,
                                                          const float* __restrict__ Hl,
                                                          float* __restrict__ out) {
    extern __shared__ char smem[];
    char*  As_h = smem + I_AH;
    char*  As_l = smem + I_AL;
    float* sa_s = (float*)(smem + I_SA);
    float* v_s[2] = { (float*)(smem + I_V), (float*)(smem + I_V) + 64 * 72 };
    float* scr1 = (float*)(smem + I_B);
    float* scr2 = scr1 + 8192;

    const int tid = threadIdx.x, wid = tid >> 5, lane = tid & 31;
    const int wy = wid >> 2, wx = wid & 3;       // 16-row tile, 64-col tile (one r)
    const int b0 = blockIdx.x * 64;

    auto load_B = [&](int gi) {
        const int tt = gi >> 6, g = gi & 63;
        const int nb = g >> 2, kc = g & 3;
        char* stp = smem + I_B + (uint32_t)(gi & 3) * B8_STG;
        #pragma unroll
        for (int q = 0; q < 2; q++) {
            int id = tid + q * 512;
            int hl = id >> 9, rem = id & 511;
            int n = rem >> 1, half = rem & 1;
            const int8_t* src = (hl ? g_B8l : g_B8h)
                + ((size_t)tt * 4096 + nb * 256 + n) * ENCD + kc * 32 + half * 16;
            cp16(smem_u32(stp + hl * 12288 + n * 48 + half * 16), src);
        }
        CP_COMMIT();
    };
    auto load_A = [&](int plane) {
        #pragma unroll
        for (int q = 0; q < 2; q++) {
            int id = tid + q * 512;
            int hl = id >> 9, rem = id & 511;
            int r = rem >> 3, s = rem & 7;
            const int8_t* src = (hl ? g_A8l : g_A8h)
                + ((size_t)plane * Bsz + b0 + r) * ENCD + s * 16;
            *(uint4*)((hl ? As_l : As_h) + r * 144 + s * 16) = *(const uint4*)src;
        }
        if (tid < 64) sa_s[tid] = g_sa[(size_t)plane * Bsz + b0 + tid];
    };

    // ---- v0 (fp32 SIMT) ----
    for (int i = tid; i < ENCD * Rr; i += 512) scr1[i] = Hf[i];      // [e*64+r]
    for (int i = tid; i < 64 * ENCD; i += 512)
        scr2[i] = g_encf[(size_t)(b0 + (i >> 7)) * ENCD + (i & 127)];
    __syncthreads();
    {
        const int r = tid & 63, q = tid >> 6;
        #pragma unroll
        for (int rr = 0; rr < 8; rr++) {
            int row = q * 8 + rr;
            float acc = 0.f;
            #pragma unroll 8
            for (int e = 0; e < ENCD; e++) acc += scr2[row * 128 + e] * scr1[e * 64 + r];
            v_s[0][row * 72 + r] = acc;
        }
    }
    __syncthreads();

    load_A(1);
    load_B(0); load_B(1); load_B(2);
    int cur = 0;

    int ahh[8][4], amd[8][4];
    #pragma unroll
    for (int j = 0; j < 8; j++)
        #pragma unroll
        for (int q = 0; q < 4; q++) { ahh[j][q] = 0; amd[j][q] = 0; }

    const int a_roff = (lane & 7) + 8 * ((lane >> 3) & 1);
    const int a_boff = 16 * (lane >> 4);
    const int b_roff = (lane & 7) + 8 * (lane >> 4);
    const int b_boff = 16 * ((lane >> 3) & 1);

    for (int t = 0; t < Tn - 2; t++) {
        if (t > 0) { __syncthreads(); load_A(t + 1); __syncthreads(); }
        for (int g = 0; g < 64; g++) {
            const int gi = t * 64 + g;
            if (gi < 638)       { CP_WAIT(2); }
            else if (gi == 638) { CP_WAIT(1); }
            else                { CP_WAIT(0); }
            __syncthreads();
            if (gi + 3 < 640) load_B(gi + 3);

            char* stp = smem + I_B + (uint32_t)(gi & 3) * B8_STG;
            const int k0 = (g & 3) * 32;

            uint32_t ah[4], al[4];
            ldmx4(ah, smem_u32(As_h + (wy * 16 + a_roff) * 144 + k0 + a_boff));
            ldmx4(al, smem_u32(As_l + (wy * 16 + a_roff) * 144 + k0 + a_boff));
            #pragma unroll
            for (int grp = 0; grp < 4; grp++) {
                const int nrow = wx * 64 + grp * 16 + b_roff;
                uint32_t bh[4], bl[4];
                ldmx4(bh, smem_u32(stp + nrow * 48 + b_boff));
                ldmx4(bl, smem_u32(stp + 12288 + nrow * 48 + b_boff));
                #pragma unroll
                for (int s2 = 0; s2 < 2; s2++) {
                    const int j = grp * 2 + s2;
                    imma(ahh[j], ah, bh + s2 * 2);
                    imma(amd[j], ah, bl + s2 * 2);
                    imma(amd[j], al, bh + s2 * 2);
                }
            }

            if ((g & 3) == 3) {
                const int nb = g >> 2;
                const int r_loc = nb * 4 + wx;
                float* vcur = v_s[cur];
                float* vnxt = v_s[cur ^ 1];
                const float* sbp = g_sb + (size_t)t * 4096 + nb * 256 + wx * 64;
                const int row0 = wy * 16 + (lane >> 2);
                float p0 = 0.f, p1 = 0.f;
                #pragma unroll
                for (int j = 0; j < 8; j++) {
                    const int p = j * 8 + (lane & 3) * 2;
                    float2 sb2 = *(const float2*)&sbp[p];
                    float f0 = ((float)ahh[j][0] + (float)amd[j][0] * 0.0078125f) * sb2.x;
                    float f1 = ((float)ahh[j][1] + (float)amd[j][1] * 0.0078125f) * sb2.y;
                    float f2 = ((float)ahh[j][2] + (float)amd[j][2] * 0.0078125f) * sb2.x;
                    float f3 = ((float)ahh[j][3] + (float)amd[j][3] * 0.0078125f) * sb2.y;
                    float2 va = *(float2*)&vcur[row0 * 72 + p];
                    float2 vb = *(float2*)&vcur[(row0 + 8) * 72 + p];
                    p0 += f0 * va.x + f1 * va.y;
                    p1 += f2 * vb.x + f3 * vb.y;
                    #pragma unroll
                    for (int q = 0; q < 4; q++) { ahh[j][q] = 0; amd[j][q] = 0; }
                }
                p0 += __shfl_xor_sync(0xffffffffu, p0, 1);
                p0 += __shfl_xor_sync(0xffffffffu, p0, 2);
                p1 += __shfl_xor_sync(0xffffffffu, p1, 1);
                p1 += __shfl_xor_sync(0xffffffffu, p1, 2);
                if ((lane & 3) == 0) {
                    vnxt[row0 * 72 + r_loc] = sa_s[row0] * p0;
                    vnxt[(row0 + 8) * 72 + r_loc] = sa_s[row0 + 8] * p1;
                }
            }
        }
        cur ^= 1;
    }

    // ---- final ----
    __syncthreads();
    for (int i = tid; i < ENCD * Rr; i += 512)
        scr1[i] = Hl[(i & 63) * ENCD + (i >> 6)];   // [e*64+p] from Hl[p,e,0]
    for (int i = tid; i < 64 * ENCD; i += 512)
        scr2[i] = g_encf[(size_t)((Tn - 1) * Bsz + b0 + (i >> 7)) * ENCD + (i & 127)];
    __syncthreads();
    {
        float* red = scr1 + 16384;
        const int row = tid >> 3, q = tid & 7;
        float partial = 0.f;
        #pragma unroll
        for (int pp = 0; pp < 8; pp++) {
            int p = q * 8 + pp;
            float last = 0.f;
            #pragma unroll 8
            for (int e = 0; e < ENCD; e++) last += scr2[row * 128 + e] * scr1[e * 64 + p];
            partial += v_s[cur][row * 72 + p] * last;
        }
        red[row * 8 + q] = partial;
        __syncthreads();
        if (tid < 64) {
            float s = 0.f;
            #pragma unroll
            for (int q2 = 0; q2 < 8; q2++) s += red[tid * 8 + q2];
            out[b0 + tid] = s;
        }
    }
}

// ================= host launcher =================
extern "C" void kernel_launch(void* const* d_in, const int* in_sizes, int n_in,
                              void* d_out, int out_size) {
    const float* x  = (const float*)d_in[0];
    const float* W1 = (const float*)d_in[1];
    const float* b1 = (const float*)d_in[2];
    const float* W2 = (const float*)d_in[3];
    const float* b2 = (const float*)d_in[4];
    const float* Hf = (const float*)d_in[5];
    const float* Hm = (const float*)d_in[6];
    const float* Hl = (const float*)d_in[7];
    float* out = (float*)d_out;

    cudaFuncSetAttribute(encoder2_kernel, cudaFuncAttributeMaxDynamicSharedMemorySize, ENC2_SMEM);
    cudaFuncSetAttribute(chain_i8_kernel, cudaFuncAttributeMaxDynamicSharedMemorySize, CHI_SMEM);

    prep_w_kernel<<<96, 256>>>(W1, W2);
    prep_hb8_kernel<<<(Tn - 2) * 64, 256>>>(Hm);
    encoder2_kernel<<<(Bsz * Tn) / 64, 256, ENC2_SMEM>>>(x, b1, b2);
    quant_enc_kernel<<<(Tn * Bsz) / 8, 256>>>();
    chain_i8_kernel<<<128, 512, CHI_SMEM>>>(Hf, Hl, out);
}

// round 12
// speedup vs baseline: 2.6542x; 2.6542x over previous
#include <cuda_runtime.h>
#include <cuda_bf16.h>
#include <mma.h>
#include <cstdint>

using namespace nvcuda;
typedef __nv_bfloat16 bf16;

#define Bsz 8192
#define Tn  12
#define DIN 64
#define HID 512
#define ENCD 128
#define Rr  64

// ================= device-global scratch =================
__device__ __align__(256) bf16  g_ench[Tn * Bsz * ENCD];   // [t][b][e] hi
__device__ __align__(256) bf16  g_encl[Tn * Bsz * ENCD];   // lo
__device__ __align__(256) bf16  g_W1hi[HID * DIN],  g_W1lo[HID * DIN];
__device__ __align__(256) bf16  g_W2hi[ENCD * HID], g_W2lo[ENCD * HID];
// H_mid as GEMM-B (hi only): [t][e][n = r*64+p]
__device__ __align__(256) bf16  g_HBh[(Tn - 2) * ENCD * Rr * Rr];

__device__ __forceinline__ uint32_t smem_u32(const void* p) {
    uint32_t a;
    asm("{ .reg .u64 t; cvta.to.shared.u64 t, %1; cvt.u32.u64 %0, t; }" : "=r"(a) : "l"(p));
    return a;
}
__device__ __forceinline__ void cp16(uint32_t dst, const void* src) {
    asm volatile("cp.async.cg.shared.global [%0], [%1], 16;" :: "r"(dst), "l"(src));
}
#define CP_COMMIT()  asm volatile("cp.async.commit_group;")
#define CP_WAIT(N)   asm volatile("cp.async.wait_group %0;" :: "n"(N))

// ---- raw MMA primitives ----
__device__ __forceinline__ void ldmx4(uint32_t* r, uint32_t a) {
    asm volatile("ldmatrix.sync.aligned.m8n8.x4.shared.b16 {%0,%1,%2,%3}, [%4];"
                 : "=r"(r[0]), "=r"(r[1]), "=r"(r[2]), "=r"(r[3]) : "r"(a));
}
__device__ __forceinline__ void ldmx4t(uint32_t* r, uint32_t a) {
    asm volatile("ldmatrix.sync.aligned.m8n8.x4.trans.shared.b16 {%0,%1,%2,%3}, [%4];"
                 : "=r"(r[0]), "=r"(r[1]), "=r"(r[2]), "=r"(r[3]) : "r"(a));
}
__device__ __forceinline__ void mma16816(float* d, const uint32_t* a, const uint32_t* b) {
    asm volatile("mma.sync.aligned.m16n8k16.row.col.f32.bf16.bf16.f32 "
                 "{%0,%1,%2,%3}, {%4,%5,%6,%7}, {%8,%9}, {%0,%1,%2,%3};"
                 : "+f"(d[0]), "+f"(d[1]), "+f"(d[2]), "+f"(d[3])
                 : "r"(a[0]), "r"(a[1]), "r"(a[2]), "r"(a[3]), "r"(b[0]), "r"(b[1]));
}

// ================= prep: W splits =================
__global__ void prep_w_kernel(const float* __restrict__ W1,
                              const float* __restrict__ W2) {
    const int n1 = HID * DIN, n2 = ENCD * HID;
    for (int i = blockIdx.x * blockDim.x + threadIdx.x; i < n1 + n2;
         i += gridDim.x * blockDim.x) {
        const float* s; bf16 *h, *l; int j;
        if (i < n1) { s = W1; h = g_W1hi; l = g_W1lo; j = i; }
        else        { s = W2; h = g_W2hi; l = g_W2lo; j = i - n1; }
        float v = s[j];
        bf16 hi = __float2bfloat16(v);
        h[j] = hi;
        l[j] = __float2bfloat16(v - __bfloat162float(hi));
    }
}

// ================= prep: Hm[t,p,e,r] -> HB[t][e][r*64+p] (hi only) =================
__global__ __launch_bounds__(256) void prep_hb_kernel(const float* __restrict__ Hm) {
    __shared__ float tile[64][65];              // [p][r]
    const int t = blockIdx.x >> 7;
    const int e = blockIdx.x & 127;
    const int tid = threadIdx.x;
    for (int i = tid; i < 64 * 64; i += 256) {
        int p = i >> 6, r = i & 63;
        tile[p][r] = Hm[(((size_t)(t * 64 + p) * 128) + e) * 64 + r];
    }
    __syncthreads();
    bf16* dh = g_HBh + (size_t)(t * 128 + e) * 4096;
    for (int c = tid; c < 4096; c += 256) {
        int r = c >> 6, p = c & 63;
        dh[c] = __float2bfloat16(tile[p][r]);
    }
}

// ================= encoder (R8 version: 256 threads, bf16x3) =================
#define EX_H 0u
#define EX_L (EX_H + 64u * 72u * 2u)
#define EH_H (EX_L + 64u * 72u * 2u)
#define EH_L (EH_H + 64u * 520u * 2u)
#define E_ST (EH_L + 64u * 520u * 2u)
#define ENC2_SMEM (E_ST + 8u * 320u * 4u)

__global__ __launch_bounds__(256, 1) void encoder2_kernel(const float* __restrict__ x,
                                                          const float* __restrict__ b1,
                                                          const float* __restrict__ b2) {
    extern __shared__ char smem[];
    bf16* xs_hi = (bf16*)(smem + EX_H);
    bf16* xs_lo = (bf16*)(smem + EX_L);
    bf16* hs_hi = (bf16*)(smem + EH_H);
    bf16* hs_lo = (bf16*)(smem + EH_L);
    float* stg_base = (float*)(smem + E_ST);

    const int tid = threadIdx.x, w = tid >> 5, lane = tid & 31;
    const int wy = w >> 2, wx = w & 3;
    const int n0 = blockIdx.x * 64;
    float* stg = stg_base + w * 320;
    const int frow = lane >> 1, fcol = (lane & 1) * 8;

    #pragma unroll
    for (int k = 0; k < 16; k++) {
        int idx = tid + k * 256;
        int r = idx >> 6, c = idx & 63;
        float v = x[(size_t)(n0 + r) * DIN + c];
        bf16 hi = __float2bfloat16(v);
        xs_hi[r * 72 + c] = hi;
        xs_lo[r * 72 + c] = __float2bfloat16(v - __bfloat162float(hi));
    }
    __syncthreads();

    #pragma unroll
    for (int pass = 0; pass < 2; pass++) {
        const int cb = wx * 128 + pass * 64;
        wmma::fragment<wmma::accumulator, 16, 16, 16, float> acc[2][4];
        #pragma unroll
        for (int rf = 0; rf < 2; rf++)
            #pragma unroll
            for (int j = 0; j < 4; j++) wmma::fill_fragment(acc[rf][j], 0.0f);
        #pragma unroll
        for (int kk = 0; kk < 4; kk++) {
            wmma::fragment<wmma::matrix_a, 16, 16, 16, bf16, wmma::row_major> ahi[2], alo[2];
            #pragma unroll
            for (int rf = 0; rf < 2; rf++) {
                wmma::load_matrix_sync(ahi[rf], xs_hi + (wy * 32 + rf * 16) * 72 + kk * 16, 72);
                wmma::load_matrix_sync(alo[rf], xs_lo + (wy * 32 + rf * 16) * 72 + kk * 16, 72);
            }
            #pragma unroll
            for (int j = 0; j < 4; j++) {
                wmma::fragment<wmma::matrix_b, 16, 16, 16, bf16, wmma::col_major> bhi, blo;
                wmma::load_matrix_sync(bhi, g_W1hi + (cb + j * 16) * DIN + kk * 16, DIN);
                wmma::load_matrix_sync(blo, g_W1lo + (cb + j * 16) * DIN + kk * 16, DIN);
                #pragma unroll
                for (int rf = 0; rf < 2; rf++) {
                    wmma::mma_sync(acc[rf][j], ahi[rf], bhi, acc[rf][j]);
                    wmma::mma_sync(acc[rf][j], alo[rf], bhi, acc[rf][j]);
                    wmma::mma_sync(acc[rf][j], ahi[rf], blo, acc[rf][j]);
                }
            }
        }
        #pragma unroll
        for (int rf = 0; rf < 2; rf++)
            #pragma unroll
            for (int j = 0; j < 4; j++) {
                wmma::store_matrix_sync(stg, acc[rf][j], 20, wmma::mem_row_major);
                __syncwarp();
                const int rbase = wy * 32 + rf * 16 + frow;
                #pragma unroll
                for (int cc = 0; cc < 8; cc++) {
                    int gc = cb + j * 16 + fcol + cc;
                    float v = fmaxf(stg[frow * 20 + fcol + cc] + b1[gc], 0.0f);
                    bf16 hi = __float2bfloat16(v);
                    hs_hi[rbase * 520 + gc] = hi;
                    hs_lo[rbase * 520 + gc] = __float2bfloat16(v - __bfloat162float(hi));
                }
                __syncwarp();
            }
    }
    __syncthreads();

    {
        wmma::fragment<wmma::accumulator, 16, 16, 16, float> acc[2][2];
        #pragma unroll
        for (int rf = 0; rf < 2; rf++)
            #pragma unroll
            for (int j = 0; j < 2; j++) wmma::fill_fragment(acc[rf][j], 0.0f);
        #pragma unroll 8
        for (int kk = 0; kk < 32; kk++) {
            wmma::fragment<wmma::matrix_a, 16, 16, 16, bf16, wmma::row_major> ahi[2], alo[2];
            #pragma unroll
            for (int rf = 0; rf < 2; rf++) {
                wmma::load_matrix_sync(ahi[rf], hs_hi + (wy * 32 + rf * 16) * 520 + kk * 16, 520);
                wmma::load_matrix_sync(alo[rf], hs_lo + (wy * 32 + rf * 16) * 520 + kk * 16, 520);
            }
            #pragma unroll
            for (int j = 0; j < 2; j++) {
                wmma::fragment<wmma::matrix_b, 16, 16, 16, bf16, wmma::col_major> bhi, blo;
                wmma::load_matrix_sync(bhi, g_W2hi + (wx * 32 + j * 16) * HID + kk * 16, HID);
                wmma::load_matrix_sync(blo, g_W2lo + (wx * 32 + j * 16) * HID + kk * 16, HID);
                #pragma unroll
                for (int rf = 0; rf < 2; rf++) {
                    wmma::mma_sync(acc[rf][j], ahi[rf], bhi, acc[rf][j]);
                    wmma::mma_sync(acc[rf][j], alo[rf], bhi, acc[rf][j]);
                    wmma::mma_sync(acc[rf][j], ahi[rf], blo, acc[rf][j]);
                }
            }
        }
        #pragma unroll
        for (int rf = 0; rf < 2; rf++)
            #pragma unroll
            for (int j = 0; j < 2; j++) {
                wmma::store_matrix_sync(stg, acc[rf][j], 20, wmma::mem_row_major);
                __syncwarp();
                const int n = n0 + wy * 32 + rf * 16 + frow;
                const int b = n / Tn, tt = n % Tn;
                #pragma unroll
                for (int cc = 0; cc < 8; cc++) {
                    int e = wx * 32 + j * 16 + fcol + cc;
                    float v = fmaxf(stg[frow * 20 + fcol + cc] + b2[e], 0.0f);
                    bf16 hi = __float2bfloat16(v);
                    g_ench[(size_t)(tt * Bsz + b) * ENCD + e] = hi;
                    g_encl[(size_t)(tt * Bsz + b) * ENCD + e] = __float2bfloat16(v - __bfloat162float(hi));
                }
                __syncwarp();
            }
    }
}

// ================= fused chain (R8 structure, 2-term bf16, B hi-only) =================
// 128 CTAs x 256 threads (8 warps, 2wy x 4wx). CTA: 64 batch rows; v in SMEM ping-pong.
// B streamed 32k x 256n hi-only chunks via 4-stage cp.async; A (hi+lo) resident per step.
#define CAPF 136
#define CBPF 264
#define F_AH 0u
#define F_AL (F_AH + 64u * CAPF * 2u)               // 17408
#define F_V  (F_AL + 64u * CAPF * 2u)               // 34816
#define F_B  (F_V + 2u * 64u * 72u * 4u)            // 71680
#define B_STG_B (32u * CBPF * 2u)                   // hi-only per stage = 16896
#define CHF_SMEM (F_B + 4u * B_STG_B)               // 139264 B

__global__ __launch_bounds__(256, 1) void chain_mma_kernel(const float* __restrict__ Hf,
                                                           const float* __restrict__ Hl,
                                                           float* __restrict__ out) {
    extern __shared__ char smem[];
    bf16* As_h = (bf16*)(smem + F_AH);
    bf16* As_l = (bf16*)(smem + F_AL);
    float* v_s[2] = { (float*)(smem + F_V), (float*)(smem + F_V) + 64 * 72 };
    float* scr1 = (float*)(smem + F_B);              // endpoint scratch (inside B region)
    float* scr2 = scr1 + 8192;

    const int tid = threadIdx.x, wid = tid >> 5, lane = tid & 31;
    const int wy = wid >> 2, wx = wid & 3;           // wy 0..1 (32 rows), wx 0..3 (64 cols)
    const int b0 = blockIdx.x * 64;

    auto load_B = [&](int gi) {
        const int tt = gi >> 6, g = gi & 63;
        const int nb = g >> 2, kc = g & 3;
        const int k0 = kc * 32, cb = nb * 256;
        const bf16* HBh = g_HBh + (size_t)tt * ENCD * 4096;
        bf16* Bh = (bf16*)(smem + F_B + (uint32_t)(gi & 3) * B_STG_B);
        #pragma unroll
        for (int q = 0; q < 4; q++) {
            int i = tid + q * 256;
            int e = i >> 5, sl = (i & 31) * 8;
            cp16(smem_u32(Bh + e * CBPF + sl), HBh + (size_t)(k0 + e) * 4096 + cb + sl);
        }
        CP_COMMIT();
    };
    auto load_A = [&](int plane) {
        const bf16* Eh = g_ench + (size_t)plane * Bsz * ENCD;
        const bf16* El = g_encl + (size_t)plane * Bsz * ENCD;
        #pragma unroll
        for (int k = 0; k < 4; k++) {
            int i = tid + k * 256;
            int r = i >> 4, sl = (i & 15) * 8;
            *(uint4*)(As_h + r * CAPF + sl) = *(const uint4*)(Eh + (size_t)(b0 + r) * ENCD + sl);
            *(uint4*)(As_l + r * CAPF + sl) = *(const uint4*)(El + (size_t)(b0 + r) * ENCD + sl);
        }
    };

    // ======== v0 (fp32 SIMT, scratch in B region) ========
    for (int i = tid; i < ENCD * Rr; i += 256) scr1[i] = Hf[i];   // [e*64+r]
    for (int i = tid; i < 64 * ENCD; i += 256) {
        int r = i >> 7, e = i & 127;
        size_t a = (size_t)(b0 + r) * ENCD + e;
        scr2[r * 128 + e] = __bfloat162float(g_ench[a]) + __bfloat162float(g_encl[a]);
    }
    __syncthreads();
    {
        const int r = tid & 63, q = tid >> 6;
        #pragma unroll
        for (int rr = 0; rr < 16; rr++) {
            int row = q * 16 + rr;
            float acc = 0.f;
            #pragma unroll 8
            for (int e = 0; e < ENCD; e++) acc += scr2[row * 128 + e] * scr1[e * 64 + r];
            v_s[0][row * 72 + r] = acc;
        }
    }
    __syncthreads();   // scratch free

    // ======== pipeline prologue ========
    load_A(1);
    load_B(0); load_B(1); load_B(2);
    int cur = 0;

    float d[2][8][4];
    #pragma unroll
    for (int rf = 0; rf < 2; rf++)
        #pragma unroll
        for (int j = 0; j < 8; j++)
            #pragma unroll
            for (int q = 0; q < 4; q++) d[rf][j][q] = 0.f;

    const int a_row = (lane & 15);
    const int a_kof = (lane >> 4) << 3;
    const int b_row = (lane & 7) + ((lane >> 3) & 1) * 8;
    const int b_nof = (lane >> 4) << 3;

    for (int t = 0; t < Tn - 2; t++) {
        if (t > 0) {
            __syncthreads();           // all compute of step t-1 done
            load_A(t + 1);
            __syncthreads();
        }
        for (int g = 0; g < 64; g++) {
            const int gi = t * 64 + g;
            if (gi < 638)      { CP_WAIT(2); }
            else if (gi == 638){ CP_WAIT(1); }
            else               { CP_WAIT(0); }
            __syncthreads();                       // stage gi ready; stage gi-1 consumed
            if (gi + 3 < 640) load_B(gi + 3);      // overwrites stage (gi-1)&3 — safe

            bf16* Bh = (bf16*)(smem + F_B + (uint32_t)(gi & 3) * B_STG_B);
            const int k0 = (g & 3) * 32;

            #pragma unroll
            for (int kk = 0; kk < 2; kk++) {
                uint32_t ah[2][4], al[2][4];
                #pragma unroll
                for (int rf = 0; rf < 2; rf++) {
                    int arow = wy * 32 + rf * 16 + a_row;
                    int acol = k0 + kk * 16 + a_kof;
                    ldmx4(ah[rf], smem_u32(As_h + arow * CAPF + acol));
                    ldmx4(al[rf], smem_u32(As_l + arow * CAPF + acol));
                }
                #pragma unroll
                for (int jj = 0; jj < 4; jj++) {
                    int brow = kk * 16 + b_row;
                    int bcol = wx * 64 + jj * 16 + b_nof;
                    uint32_t bh[4];
                    ldmx4t(bh, smem_u32(Bh + brow * CBPF + bcol));
                    #pragma unroll
                    for (int s2 = 0; s2 < 2; s2++) {
                        const int j = jj * 2 + s2;
                        #pragma unroll
                        for (int rf = 0; rf < 2; rf++) {
                            mma16816(d[rf][j], ah[rf], bh + s2 * 2);
                            mma16816(d[rf][j], al[rf], bh + s2 * 2);
                        }
                    }
                }
            }

            if ((g & 3) == 3) {
                // register epilogue: v_new[row, r] = sum_p D[row, p] * v[row, p]
                const int nb = g >> 2;
                const int r_loc = nb * 4 + wx;
                float* vcur = v_s[cur];
                float* vnxt = v_s[cur ^ 1];
                #pragma unroll
                for (int rf = 0; rf < 2; rf++) {
                    const int row0 = wy * 32 + rf * 16 + (lane >> 2);
                    float p0 = 0.f, p1 = 0.f;
                    #pragma unroll
                    for (int j = 0; j < 8; j++) {
                        const int p = j * 8 + (lane & 3) * 2;
                        float2 va = *(float2*)&vcur[row0 * 72 + p];
                        float2 vb = *(float2*)&vcur[(row0 + 8) * 72 + p];
                        p0 += d[rf][j][0] * va.x + d[rf][j][1] * va.y;
                        p1 += d[rf][j][2] * vb.x + d[rf][j][3] * vb.y;
                        d[rf][j][0] = 0.f; d[rf][j][1] = 0.f;
                        d[rf][j][2] = 0.f; d[rf][j][3] = 0.f;
                    }
                    p0 += __shfl_xor_sync(0xffffffffu, p0, 1);
                    p0 += __shfl_xor_sync(0xffffffffu, p0, 2);
                    p1 += __shfl_xor_sync(0xffffffffu, p1, 1);
                    p1 += __shfl_xor_sync(0xffffffffu, p1, 2);
                    if ((lane & 3) == 0) {
                        vnxt[row0 * 72 + r_loc] = p0;
                        vnxt[(row0 + 8) * 72 + r_loc] = p1;
                    }
                }
            }
        }
        cur ^= 1;
    }

    // ======== final: out[b] = sum_p v[b,p] * (sum_e enc11[b,e] * Hl[p,e]) ========
    __syncthreads();           // pipeline fully drained; B region free
    for (int i = tid; i < ENCD * Rr; i += 256) {
        int e = i >> 6, p = i & 63;
        scr1[i] = Hl[p * ENCD + e];                 // transposed [e*64+p]
    }
    {
        const bf16* Eh = g_ench + (size_t)(Tn - 1) * Bsz * ENCD;
        const bf16* El = g_encl + (size_t)(Tn - 1) * Bsz * ENCD;
        for (int i = tid; i < 64 * ENCD; i += 256) {
            int r = i >> 7, e = i & 127;
            size_t a = (size_t)(b0 + r) * ENCD + e;
            scr2[r * 128 + e] = __bfloat162float(Eh[a]) + __bfloat162float(El[a]);
        }
    }
    __syncthreads();
    {
        float* red = scr1 + 8192 + 8192;            // 256 floats, inside B region
        const int row = tid >> 2, q = tid & 3;
        float partial = 0.f;
        #pragma unroll
        for (int pp = 0; pp < 16; pp++) {
            int p = q * 16 + pp;
            float last = 0.f;
            #pragma unroll 8
            for (int e = 0; e < ENCD; e++) last += scr2[row * 128 + e] * scr1[e * 64 + p];
            partial += v_s[cur][row * 72 + p] * last;
        }
        red[row * 4 + q] = partial;
        __syncthreads();
        if (tid < 64)
            out[b0 + tid] = red[tid * 4 + 0] + red[tid * 4 + 1]
                          + red[tid * 4 + 2] + red[tid * 4 + 3];
    }
}

// ================= host launcher =================
extern "C" void kernel_launch(void* const* d_in, const int* in_sizes, int n_in,
                              void* d_out, int out_size) {
    const float* x  = (const float*)d_in[0];
    const float* W1 = (const float*)d_in[1];
    const float* b1 = (const float*)d_in[2];
    const float* W2 = (const float*)d_in[3];
    const float* b2 = (const float*)d_in[4];
    const float* Hf = (const float*)d_in[5];
    const float* Hm = (const float*)d_in[6];
    const float* Hl = (const float*)d_in[7];
    float* out = (float*)d_out;

    cudaFuncSetAttribute(encoder2_kernel,  cudaFuncAttributeMaxDynamicSharedMemorySize, ENC2_SMEM);
    cudaFuncSetAttribute(chain_mma_kernel, cudaFuncAttributeMaxDynamicSharedMemorySize, CHF_SMEM);

    prep_w_kernel<<<96, 256>>>(W1, W2);
    prep_hb_kernel<<<(Tn - 2) * ENCD, 256>>>(Hm);
    encoder2_kernel<<<(Bsz * Tn) / 64, 256, ENC2_SMEM>>>(x, b1, b2);
    chain_mma_kernel<<<128, 256, CHF_SMEM>>>(Hf, Hl, out);
}

// round 13
// speedup vs baseline: 3.7678x; 1.4195x over previous
#include <cuda_runtime.h>
#include <cuda_bf16.h>
#include <mma.h>
#include <cstdint>

using namespace nvcuda;
typedef __nv_bfloat16 bf16;

#define Bsz 8192
#define Tn  12
#define DIN 64
#define HID 512
#define ENCD 128
#define Rr  64

// ================= device-global scratch =================
__device__ __align__(256) bf16  g_ench[Tn * Bsz * ENCD];   // [t][b][e] hi
__device__ __align__(256) bf16  g_encl[Tn * Bsz * ENCD];   // lo (for exact v0/final)
__device__ __align__(256) bf16  g_W1hi[HID * DIN];
__device__ __align__(256) bf16  g_W2hi[ENCD * HID];
// H_mid as GEMM-B (hi only): [t][e][n = r*64+p]
__device__ __align__(256) bf16  g_HBh[(Tn - 2) * ENCD * Rr * Rr];

__device__ __forceinline__ uint32_t smem_u32(const void* p) {
    uint32_t a;
    asm("{ .reg .u64 t; cvta.to.shared.u64 t, %1; cvt.u32.u64 %0, t; }" : "=r"(a) : "l"(p));
    return a;
}
__device__ __forceinline__ void cp16(uint32_t dst, const void* src) {
    asm volatile("cp.async.cg.shared.global [%0], [%1], 16;" :: "r"(dst), "l"(src));
}
#define CP_COMMIT()  asm volatile("cp.async.commit_group;")
#define CP_WAIT(N)   asm volatile("cp.async.wait_group %0;" :: "n"(N))

// ---- raw MMA primitives ----
__device__ __forceinline__ void ldmx4(uint32_t* r, uint32_t a) {
    asm volatile("ldmatrix.sync.aligned.m8n8.x4.shared.b16 {%0,%1,%2,%3}, [%4];"
                 : "=r"(r[0]), "=r"(r[1]), "=r"(r[2]), "=r"(r[3]) : "r"(a));
}
__device__ __forceinline__ void ldmx4t(uint32_t* r, uint32_t a) {
    asm volatile("ldmatrix.sync.aligned.m8n8.x4.trans.shared.b16 {%0,%1,%2,%3}, [%4];"
                 : "=r"(r[0]), "=r"(r[1]), "=r"(r[2]), "=r"(r[3]) : "r"(a));
}
__device__ __forceinline__ void mma16816(float* d, const uint32_t* a, const uint32_t* b) {
    asm volatile("mma.sync.aligned.m16n8k16.row.col.f32.bf16.bf16.f32 "
                 "{%0,%1,%2,%3}, {%4,%5,%6,%7}, {%8,%9}, {%0,%1,%2,%3};"
                 : "+f"(d[0]), "+f"(d[1]), "+f"(d[2]), "+f"(d[3])
                 : "r"(a[0]), "r"(a[1]), "r"(a[2]), "r"(a[3]), "r"(b[0]), "r"(b[1]));
}

// ================= prep: W hi =================
__global__ void prep_w_kernel(const float* __restrict__ W1,
                              const float* __restrict__ W2) {
    const int n1 = HID * DIN, n2 = ENCD * HID;
    for (int i = blockIdx.x * blockDim.x + threadIdx.x; i < n1 + n2;
         i += gridDim.x * blockDim.x) {
        if (i < n1) g_W1hi[i] = __float2bfloat16(W1[i]);
        else        g_W2hi[i - n1] = __float2bfloat16(W2[i - n1]);
    }
}

// ================= prep: Hm[t,p,e,r] -> HB[t][e][r*64+p] (hi only) =================
__global__ __launch_bounds__(256) void prep_hb_kernel(const float* __restrict__ Hm) {
    __shared__ float tile[64][65];              // [p][r]
    const int t = blockIdx.x >> 7;
    const int e = blockIdx.x & 127;
    const int tid = threadIdx.x;
    for (int i = tid; i < 64 * 64; i += 256) {
        int p = i >> 6, r = i & 63;
        tile[p][r] = Hm[(((size_t)(t * 64 + p) * 128) + e) * 64 + r];
    }
    __syncthreads();
    bf16* dh = g_HBh + (size_t)(t * 128 + e) * 4096;
    for (int c = tid; c < 4096; c += 256) {
        int r = c >> 6, p = c & 63;
        dh[c] = __float2bfloat16(tile[p][r]);
    }
}

// ================= encoder (256 threads, 2-term: (a_hi+a_lo)·b_hi) =================
#define EX_H 0u
#define EX_L (EX_H + 64u * 72u * 2u)
#define EH_H (EX_L + 64u * 72u * 2u)
#define EH_L (EH_H + 64u * 520u * 2u)
#define E_ST (EH_L + 64u * 520u * 2u)
#define ENC2_SMEM (E_ST + 8u * 320u * 4u)

__global__ __launch_bounds__(256, 1) void encoder2_kernel(const float* __restrict__ x,
                                                          const float* __restrict__ b1,
                                                          const float* __restrict__ b2) {
    extern __shared__ char smem[];
    bf16* xs_hi = (bf16*)(smem + EX_H);
    bf16* xs_lo = (bf16*)(smem + EX_L);
    bf16* hs_hi = (bf16*)(smem + EH_H);
    bf16* hs_lo = (bf16*)(smem + EH_L);
    float* stg_base = (float*)(smem + E_ST);

    const int tid = threadIdx.x, w = tid >> 5, lane = tid & 31;
    const int wy = w >> 2, wx = w & 3;
    const int n0 = blockIdx.x * 64;
    float* stg = stg_base + w * 320;
    const int frow = lane >> 1, fcol = (lane & 1) * 8;

    #pragma unroll
    for (int k = 0; k < 16; k++) {
        int idx = tid + k * 256;
        int r = idx >> 6, c = idx & 63;
        float v = x[(size_t)(n0 + r) * DIN + c];
        bf16 hi = __float2bfloat16(v);
        xs_hi[r * 72 + c] = hi;
        xs_lo[r * 72 + c] = __float2bfloat16(v - __bfloat162float(hi));
    }
    __syncthreads();

    #pragma unroll
    for (int pass = 0; pass < 2; pass++) {
        const int cb = wx * 128 + pass * 64;
        wmma::fragment<wmma::accumulator, 16, 16, 16, float> acc[2][4];
        #pragma unroll
        for (int rf = 0; rf < 2; rf++)
            #pragma unroll
            for (int j = 0; j < 4; j++) wmma::fill_fragment(acc[rf][j], 0.0f);
        #pragma unroll
        for (int kk = 0; kk < 4; kk++) {
            wmma::fragment<wmma::matrix_a, 16, 16, 16, bf16, wmma::row_major> ahi[2], alo[2];
            #pragma unroll
            for (int rf = 0; rf < 2; rf++) {
                wmma::load_matrix_sync(ahi[rf], xs_hi + (wy * 32 + rf * 16) * 72 + kk * 16, 72);
                wmma::load_matrix_sync(alo[rf], xs_lo + (wy * 32 + rf * 16) * 72 + kk * 16, 72);
            }
            #pragma unroll
            for (int j = 0; j < 4; j++) {
                wmma::fragment<wmma::matrix_b, 16, 16, 16, bf16, wmma::col_major> bhi;
                wmma::load_matrix_sync(bhi, g_W1hi + (cb + j * 16) * DIN + kk * 16, DIN);
                #pragma unroll
                for (int rf = 0; rf < 2; rf++) {
                    wmma::mma_sync(acc[rf][j], ahi[rf], bhi, acc[rf][j]);
                    wmma::mma_sync(acc[rf][j], alo[rf], bhi, acc[rf][j]);
                }
            }
        }
        #pragma unroll
        for (int rf = 0; rf < 2; rf++)
            #pragma unroll
            for (int j = 0; j < 4; j++) {
                wmma::store_matrix_sync(stg, acc[rf][j], 20, wmma::mem_row_major);
                __syncwarp();
                const int rbase = wy * 32 + rf * 16 + frow;
                #pragma unroll
                for (int cc = 0; cc < 8; cc++) {
                    int gc = cb + j * 16 + fcol + cc;
                    float v = fmaxf(stg[frow * 20 + fcol + cc] + b1[gc], 0.0f);
                    bf16 hi = __float2bfloat16(v);
                    hs_hi[rbase * 520 + gc] = hi;
                    hs_lo[rbase * 520 + gc] = __float2bfloat16(v - __bfloat162float(hi));
                }
                __syncwarp();
            }
    }
    __syncthreads();

    {
        wmma::fragment<wmma::accumulator, 16, 16, 16, float> acc[2][2];
        #pragma unroll
        for (int rf = 0; rf < 2; rf++)
            #pragma unroll
            for (int j = 0; j < 2; j++) wmma::fill_fragment(acc[rf][j], 0.0f);
        #pragma unroll 8
        for (int kk = 0; kk < 32; kk++) {
            wmma::fragment<wmma::matrix_a, 16, 16, 16, bf16, wmma::row_major> ahi[2], alo[2];
            #pragma unroll
            for (int rf = 0; rf < 2; rf++) {
                wmma::load_matrix_sync(ahi[rf], hs_hi + (wy * 32 + rf * 16) * 520 + kk * 16, 520);
                wmma::load_matrix_sync(alo[rf], hs_lo + (wy * 32 + rf * 16) * 520 + kk * 16, 520);
            }
            #pragma unroll
            for (int j = 0; j < 2; j++) {
                wmma::fragment<wmma::matrix_b, 16, 16, 16, bf16, wmma::col_major> bhi;
                wmma::load_matrix_sync(bhi, g_W2hi + (wx * 32 + j * 16) * HID + kk * 16, HID);
                #pragma unroll
                for (int rf = 0; rf < 2; rf++) {
                    wmma::mma_sync(acc[rf][j], ahi[rf], bhi, acc[rf][j]);
                    wmma::mma_sync(acc[rf][j], alo[rf], bhi, acc[rf][j]);
                }
            }
        }
        #pragma unroll
        for (int rf = 0; rf < 2; rf++)
            #pragma unroll
            for (int j = 0; j < 2; j++) {
                wmma::store_matrix_sync(stg, acc[rf][j], 20, wmma::mem_row_major);
                __syncwarp();
                const int n = n0 + wy * 32 + rf * 16 + frow;
                const int b = n / Tn, tt = n % Tn;
                #pragma unroll
                for (int cc = 0; cc < 8; cc++) {
                    int e = wx * 32 + j * 16 + fcol + cc;
                    float v = fmaxf(stg[frow * 20 + fcol + cc] + b2[e], 0.0f);
                    bf16 hi = __float2bfloat16(v);
                    g_ench[(size_t)(tt * Bsz + b) * ENCD + e] = hi;
                    g_encl[(size_t)(tt * Bsz + b) * ENCD + e] = __float2bfloat16(v - __bfloat162float(hi));
                }
                __syncwarp();
            }
    }
}

// ================= fused chain: single-term bf16, big-chunk (K=128 x 256n) =================
// 128 CTAs x 256 threads (8 warps, 2wy x 4wx). Big chunk = one n-block, full K.
// 2-stage double buffer; A (hi) resident per step; register epilogue per chunk.
#define CAPF 136
#define CBPF 264
#define F_AH 0u
#define F_V  (F_AH + 64u * CAPF * 2u)               // 17408
#define F_B  (F_V + 2u * 64u * 72u * 4u)            // 54272
#define B_STG_B (128u * CBPF * 2u)                  // 67584 per stage
#define CHF_SMEM (F_B + 2u * B_STG_B)               // 189440 B

__global__ __launch_bounds__(256, 1) void chain_mma_kernel(const float* __restrict__ Hf,
                                                           const float* __restrict__ Hl,
                                                           float* __restrict__ out) {
    extern __shared__ char smem[];
    bf16* As_h = (bf16*)(smem + F_AH);
    float* v_s[2] = { (float*)(smem + F_V), (float*)(smem + F_V) + 64 * 72 };
    float* scr1 = (float*)(smem + F_B);              // endpoint scratch (inside B region)
    float* scr2 = scr1 + 8192;

    const int tid = threadIdx.x, wid = tid >> 5, lane = tid & 31;
    const int wy = wid >> 2, wx = wid & 3;           // 32-row tile, 64-col tile (one r)
    const int b0 = blockIdx.x * 64;

    // big chunk gi = t*16 + nb; stage gi&1; loads 128 e-rows x 256 cols (hi)
    auto load_B = [&](int gi) {
        const int tt = gi >> 4, nb = gi & 15;
        const int cb = nb * 256;
        const bf16* HBh = g_HBh + (size_t)tt * ENCD * 4096;
        bf16* Bh = (bf16*)(smem + F_B + (uint32_t)(gi & 1) * B_STG_B);
        #pragma unroll
        for (int q = 0; q < 16; q++) {
            int i = tid + q * 256;
            int e = i >> 5, sl = (i & 31) * 8;
            cp16(smem_u32(Bh + e * CBPF + sl), HBh + (size_t)e * 4096 + cb + sl);
        }
        CP_COMMIT();
    };
    auto load_A = [&](int plane) {
        const bf16* Eh = g_ench + (size_t)plane * Bsz * ENCD;
        #pragma unroll
        for (int k = 0; k < 4; k++) {
            int i = tid + k * 256;
            int r = i >> 4, sl = (i & 15) * 8;
            *(uint4*)(As_h + r * CAPF + sl) = *(const uint4*)(Eh + (size_t)(b0 + r) * ENCD + sl);
        }
    };

    // ======== v0 (fp32 SIMT, exact enc = hi+lo) ========
    for (int i = tid; i < ENCD * Rr; i += 256) scr1[i] = Hf[i];   // [e*64+r]
    for (int i = tid; i < 64 * ENCD; i += 256) {
        int r = i >> 7, e = i & 127;
        size_t a = (size_t)(b0 + r) * ENCD + e;
        scr2[r * 128 + e] = __bfloat162float(g_ench[a]) + __bfloat162float(g_encl[a]);
    }
    __syncthreads();
    {
        const int r = tid & 63, q = tid >> 6;
        #pragma unroll
        for (int rr = 0; rr < 16; rr++) {
            int row = q * 16 + rr;
            float acc = 0.f;
            #pragma unroll 8
            for (int e = 0; e < ENCD; e++) acc += scr2[row * 128 + e] * scr1[e * 64 + r];
            v_s[0][row * 72 + r] = acc;
        }
    }
    __syncthreads();   // scratch free

    // ======== pipeline prologue ========
    load_A(1);
    load_B(0);
    int cur = 0;

    float d[2][8][4];
    #pragma unroll
    for (int rf = 0; rf < 2; rf++)
        #pragma unroll
        for (int j = 0; j < 8; j++)
            #pragma unroll
            for (int q = 0; q < 4; q++) d[rf][j][q] = 0.f;

    const int a_row = (lane & 15);
    const int a_kof = (lane >> 4) << 3;
    const int b_row = (lane & 7) + ((lane >> 3) & 1) * 8;
    const int b_nof = (lane >> 4) << 3;

    for (int t = 0; t < Tn - 2; t++) {
        if (t > 0) {
            __syncthreads();           // step t-1 compute + v writes complete
            load_A(t + 1);
            __syncthreads();
        }
        for (int g = 0; g < 16; g++) {
            const int gi = t * 16 + g;
            CP_WAIT(0);
            __syncthreads();                       // stage gi ready; stage gi-1 consumed
            if (gi + 1 < 160) load_B(gi + 1);      // fill other stage during compute

            bf16* Bh = (bf16*)(smem + F_B + (uint32_t)(gi & 1) * B_STG_B);

            #pragma unroll
            for (int kk = 0; kk < 8; kk++) {
                uint32_t ah[2][4];
                #pragma unroll
                for (int rf = 0; rf < 2; rf++) {
                    int arow = wy * 32 + rf * 16 + a_row;
                    ldmx4(ah[rf], smem_u32(As_h + arow * CAPF + kk * 16 + a_kof));
                }
                #pragma unroll
                for (int jj = 0; jj < 4; jj++) {
                    int brow = kk * 16 + b_row;
                    int bcol = wx * 64 + jj * 16 + b_nof;
                    uint32_t bh[4];
                    ldmx4t(bh, smem_u32(Bh + brow * CBPF + bcol));
                    #pragma unroll
                    for (int s2 = 0; s2 < 2; s2++) {
                        const int j = jj * 2 + s2;
                        #pragma unroll
                        for (int rf = 0; rf < 2; rf++)
                            mma16816(d[rf][j], ah[rf], bh + s2 * 2);
                    }
                }
            }

            // register epilogue: v_new[row, r] = sum_p D[row, p] * v[row, p]
            {
                const int r_loc = g * 4 + wx;
                float* vcur = v_s[cur];
                float* vnxt = v_s[cur ^ 1];
                #pragma unroll
                for (int rf = 0; rf < 2; rf++) {
                    const int row0 = wy * 32 + rf * 16 + (lane >> 2);
                    float p0 = 0.f, p1 = 0.f;
                    #pragma unroll
                    for (int j = 0; j < 8; j++) {
                        const int p = j * 8 + (lane & 3) * 2;
                        float2 va = *(float2*)&vcur[row0 * 72 + p];
                        float2 vb = *(float2*)&vcur[(row0 + 8) * 72 + p];
                        p0 += d[rf][j][0] * va.x + d[rf][j][1] * va.y;
                        p1 += d[rf][j][2] * vb.x + d[rf][j][3] * vb.y;
                        d[rf][j][0] = 0.f; d[rf][j][1] = 0.f;
                        d[rf][j][2] = 0.f; d[rf][j][3] = 0.f;
                    }
                    p0 += __shfl_xor_sync(0xffffffffu, p0, 1);
                    p0 += __shfl_xor_sync(0xffffffffu, p0, 2);
                    p1 += __shfl_xor_sync(0xffffffffu, p1, 1);
                    p1 += __shfl_xor_sync(0xffffffffu, p1, 2);
                    if ((lane & 3) == 0) {
                        vnxt[row0 * 72 + r_loc] = p0;
                        vnxt[(row0 + 8) * 72 + r_loc] = p1;
                    }
                }
            }
        }
        cur ^= 1;
    }

    // ======== final: out[b] = sum_p v[b,p] * (sum_e enc11[b,e] * Hl[p,e]) ========
    __syncthreads();           // pipeline drained; B region free
    for (int i = tid; i < ENCD * Rr; i += 256) {
        int e = i >> 6, p = i & 63;
        scr1[i] = Hl[p * ENCD + e];                 // transposed [e*64+p]
    }
    {
        const bf16* Eh = g_ench + (size_t)(Tn - 1) * Bsz * ENCD;
        const bf16* El = g_encl + (size_t)(Tn - 1) * Bsz * ENCD;
        for (int i = tid; i < 64 * ENCD; i += 256) {
            int r = i >> 7, e = i & 127;
            size_t a = (size_t)(b0 + r) * ENCD + e;
            scr2[r * 128 + e] = __bfloat162float(Eh[a]) + __bfloat162float(El[a]);
        }
    }
    __syncthreads();
    {
        float* red = scr1 + 8192 + 8192;            // 256 floats, inside B region
        const int row = tid >> 2, q = tid & 3;
        float partial = 0.f;
        #pragma unroll
        for (int pp = 0; pp < 16; pp++) {
            int p = q * 16 + pp;
            float last = 0.f;
            #pragma unroll 8
            for (int e = 0; e < ENCD; e++) last += scr2[row * 128 + e] * scr1[e * 64 + p];
            partial += v_s[cur][row * 72 + p] * last;
        }
        red[row * 4 + q] = partial;
        __syncthreads();
        if (tid < 64)
            out[b0 + tid] = red[tid * 4 + 0] + red[tid * 4 + 1]
                          + red[tid * 4 + 2] + red[tid * 4 + 3];
    }
}

// ================= host launcher =================
extern "C" void kernel_launch(void* const* d_in, const int* in_sizes, int n_in,
                              void* d_out, int out_size) {
    const float* x  = (const float*)d_in[0];
    const float* W1 = (const float*)d_in[1];
    const float* b1 = (const float*)d_in[2];
    const float* W2 = (const float*)d_in[3];
    const float* b2 = (const float*)d_in[4];
    const float* Hf = (const float*)d_in[5];
    const float* Hm = (const float*)d_in[6];
    const float* Hl = (const float*)d_in[7];
    float* out = (float*)d_out;

    cudaFuncSetAttribute(encoder2_kernel,  cudaFuncAttributeMaxDynamicSharedMemorySize, ENC2_SMEM);
    cudaFuncSetAttribute(chain_mma_kernel, cudaFuncAttributeMaxDynamicSharedMemorySize, CHF_SMEM);

    prep_w_kernel<<<96, 256>>>(W1, W2);
    prep_hb_kernel<<<(Tn - 2) * ENCD, 256>>>(Hm);
    encoder2_kernel<<<(Bsz * Tn) / 64, 256, ENC2_SMEM>>>(x, b1, b2);
    chain_mma_kernel<<<128, 256, CHF_SMEM>>>(Hf, Hl, out);
}

// round 14
// speedup vs baseline: 4.0787x; 1.0825x over previous
#include <cuda_runtime.h>
#include <cuda_bf16.h>
#include <mma.h>
#include <cstdint>

using namespace nvcuda;
typedef __nv_bfloat16 bf16;

#define Bsz 8192
#define Tn  12
#define DIN 64
#define HID 512
#define ENCD 128
#define Rr  64

// ================= device-global scratch =================
__device__ __align__(256) bf16  g_ench[Tn * Bsz * ENCD];   // [t][b][e] hi
__device__ __align__(256) bf16  g_encl[Tn * Bsz * ENCD];   // lo (exact v0/final only)
__device__ __align__(256) bf16  g_W1hi[HID * DIN];
__device__ __align__(256) bf16  g_W2hi[ENCD * HID];
// H_mid as GEMM-B (hi only): [t][e][n = r*64+p]
__device__ __align__(256) bf16  g_HBh[(Tn - 2) * ENCD * Rr * Rr];

__device__ __forceinline__ uint32_t smem_u32(const void* p) {
    uint32_t a;
    asm("{ .reg .u64 t; cvta.to.shared.u64 t, %1; cvt.u32.u64 %0, t; }" : "=r"(a) : "l"(p));
    return a;
}
__device__ __forceinline__ void cp16(uint32_t dst, const void* src) {
    asm volatile("cp.async.cg.shared.global [%0], [%1], 16;" :: "r"(dst), "l"(src));
}
#define CP_COMMIT()  asm volatile("cp.async.commit_group;")
#define CP_WAIT(N)   asm volatile("cp.async.wait_group %0;" :: "n"(N))

// ---- raw MMA primitives ----
__device__ __forceinline__ void ldmx4(uint32_t* r, uint32_t a) {
    asm volatile("ldmatrix.sync.aligned.m8n8.x4.shared.b16 {%0,%1,%2,%3}, [%4];"
                 : "=r"(r[0]), "=r"(r[1]), "=r"(r[2]), "=r"(r[3]) : "r"(a));
}
__device__ __forceinline__ void ldmx4t(uint32_t* r, uint32_t a) {
    asm volatile("ldmatrix.sync.aligned.m8n8.x4.trans.shared.b16 {%0,%1,%2,%3}, [%4];"
                 : "=r"(r[0]), "=r"(r[1]), "=r"(r[2]), "=r"(r[3]) : "r"(a));
}
__device__ __forceinline__ void mma16816(float* d, const uint32_t* a, const uint32_t* b) {
    asm volatile("mma.sync.aligned.m16n8k16.row.col.f32.bf16.bf16.f32 "
                 "{%0,%1,%2,%3}, {%4,%5,%6,%7}, {%8,%9}, {%0,%1,%2,%3};"
                 : "+f"(d[0]), "+f"(d[1]), "+f"(d[2]), "+f"(d[3])
                 : "r"(a[0]), "r"(a[1]), "r"(a[2]), "r"(a[3]), "r"(b[0]), "r"(b[1]));
}

// ================= prep: W hi =================
__global__ void prep_w_kernel(const float* __restrict__ W1,
                              const float* __restrict__ W2) {
    const int n1 = HID * DIN, n2 = ENCD * HID;
    for (int i = blockIdx.x * blockDim.x + threadIdx.x; i < n1 + n2;
         i += gridDim.x * blockDim.x) {
        if (i < n1) g_W1hi[i] = __float2bfloat16(W1[i]);
        else        g_W2hi[i - n1] = __float2bfloat16(W2[i - n1]);
    }
}

// ================= prep: Hm[t,p,e,r] -> HB[t][e][r*64+p] (hi only) =================
__global__ __launch_bounds__(256) void prep_hb_kernel(const float* __restrict__ Hm) {
    __shared__ float tile[64][65];              // [p][r]
    const int t = blockIdx.x >> 7;
    const int e = blockIdx.x & 127;
    const int tid = threadIdx.x;
    for (int i = tid; i < 64 * 64; i += 256) {
        int p = i >> 6, r = i & 63;
        tile[p][r] = Hm[(((size_t)(t * 64 + p) * 128) + e) * 64 + r];
    }
    __syncthreads();
    bf16* dh = g_HBh + (size_t)(t * 128 + e) * 4096;
    for (int c = tid; c < 4096; c += 256) {
        int r = c >> 6, p = c & 63;
        dh[c] = __float2bfloat16(tile[p][r]);
    }
}

// ================= encoder (256 threads, single-term hi x hi) =================
#define EX_H 0u
#define EH_H (EX_H + 64u * 72u * 2u)               // 9216
#define E_ST (EH_H + 64u * 520u * 2u)              // 75776
#define ENC2_SMEM (E_ST + 8u * 320u * 4u)          // 86016

__global__ __launch_bounds__(256, 1) void encoder2_kernel(const float* __restrict__ x,
                                                          const float* __restrict__ b1,
                                                          const float* __restrict__ b2) {
    extern __shared__ char smem[];
    bf16* xs_hi = (bf16*)(smem + EX_H);
    bf16* hs_hi = (bf16*)(smem + EH_H);
    float* stg_base = (float*)(smem + E_ST);

    const int tid = threadIdx.x, w = tid >> 5, lane = tid & 31;
    const int wy = w >> 2, wx = w & 3;
    const int n0 = blockIdx.x * 64;
    float* stg = stg_base + w * 320;
    const int frow = lane >> 1, fcol = (lane & 1) * 8;

    #pragma unroll
    for (int k = 0; k < 16; k++) {
        int idx = tid + k * 256;
        int r = idx >> 6, c = idx & 63;
        xs_hi[r * 72 + c] = __float2bfloat16(x[(size_t)(n0 + r) * DIN + c]);
    }
    __syncthreads();

    #pragma unroll
    for (int pass = 0; pass < 2; pass++) {
        const int cb = wx * 128 + pass * 64;
        wmma::fragment<wmma::accumulator, 16, 16, 16, float> acc[2][4];
        #pragma unroll
        for (int rf = 0; rf < 2; rf++)
            #pragma unroll
            for (int j = 0; j < 4; j++) wmma::fill_fragment(acc[rf][j], 0.0f);
        #pragma unroll
        for (int kk = 0; kk < 4; kk++) {
            wmma::fragment<wmma::matrix_a, 16, 16, 16, bf16, wmma::row_major> ahi[2];
            #pragma unroll
            for (int rf = 0; rf < 2; rf++)
                wmma::load_matrix_sync(ahi[rf], xs_hi + (wy * 32 + rf * 16) * 72 + kk * 16, 72);
            #pragma unroll
            for (int j = 0; j < 4; j++) {
                wmma::fragment<wmma::matrix_b, 16, 16, 16, bf16, wmma::col_major> bhi;
                wmma::load_matrix_sync(bhi, g_W1hi + (cb + j * 16) * DIN + kk * 16, DIN);
                #pragma unroll
                for (int rf = 0; rf < 2; rf++)
                    wmma::mma_sync(acc[rf][j], ahi[rf], bhi, acc[rf][j]);
            }
        }
        #pragma unroll
        for (int rf = 0; rf < 2; rf++)
            #pragma unroll
            for (int j = 0; j < 4; j++) {
                wmma::store_matrix_sync(stg, acc[rf][j], 20, wmma::mem_row_major);
                __syncwarp();
                const int rbase = wy * 32 + rf * 16 + frow;
                #pragma unroll
                for (int cc = 0; cc < 8; cc++) {
                    int gc = cb + j * 16 + fcol + cc;
                    float v = fmaxf(stg[frow * 20 + fcol + cc] + b1[gc], 0.0f);
                    hs_hi[rbase * 520 + gc] = __float2bfloat16(v);
                }
                __syncwarp();
            }
    }
    __syncthreads();

    {
        wmma::fragment<wmma::accumulator, 16, 16, 16, float> acc[2][2];
        #pragma unroll
        for (int rf = 0; rf < 2; rf++)
            #pragma unroll
            for (int j = 0; j < 2; j++) wmma::fill_fragment(acc[rf][j], 0.0f);
        #pragma unroll 8
        for (int kk = 0; kk < 32; kk++) {
            wmma::fragment<wmma::matrix_a, 16, 16, 16, bf16, wmma::row_major> ahi[2];
            #pragma unroll
            for (int rf = 0; rf < 2; rf++)
                wmma::load_matrix_sync(ahi[rf], hs_hi + (wy * 32 + rf * 16) * 520 + kk * 16, 520);
            #pragma unroll
            for (int j = 0; j < 2; j++) {
                wmma::fragment<wmma::matrix_b, 16, 16, 16, bf16, wmma::col_major> bhi;
                wmma::load_matrix_sync(bhi, g_W2hi + (wx * 32 + j * 16) * HID + kk * 16, HID);
                #pragma unroll
                for (int rf = 0; rf < 2; rf++)
                    wmma::mma_sync(acc[rf][j], ahi[rf], bhi, acc[rf][j]);
            }
        }
        #pragma unroll
        for (int rf = 0; rf < 2; rf++)
            #pragma unroll
            for (int j = 0; j < 2; j++) {
                wmma::store_matrix_sync(stg, acc[rf][j], 20, wmma::mem_row_major);
                __syncwarp();
                const int n = n0 + wy * 32 + rf * 16 + frow;
                const int b = n / Tn, tt = n % Tn;
                #pragma unroll
                for (int cc = 0; cc < 8; cc++) {
                    int e = wx * 32 + j * 16 + fcol + cc;
                    float v = fmaxf(stg[frow * 20 + fcol + cc] + b2[e], 0.0f);
                    bf16 hi = __float2bfloat16(v);
                    g_ench[(size_t)(tt * Bsz + b) * ENCD + e] = hi;
                    g_encl[(size_t)(tt * Bsz + b) * ENCD + e] = __float2bfloat16(v - __bfloat162float(hi));
                }
                __syncwarp();
            }
    }
}

// ================= fused chain: single-term bf16, big-chunk, hoisted A frags =================
#define CAPF 136
#define CBPF 264
#define F_AH 0u
#define F_V  (F_AH + 64u * CAPF * 2u)               // 17408
#define F_B  (F_V + 2u * 64u * 72u * 4u)            // 54272
#define B_STG_B (128u * CBPF * 2u)                  // 67584 per stage
#define CHF_SMEM (F_B + 2u * B_STG_B)               // 189440 B

__global__ __launch_bounds__(256, 1) void chain_mma_kernel(const float* __restrict__ Hf,
                                                           const float* __restrict__ Hl,
                                                           float* __restrict__ out) {
    extern __shared__ char smem[];
    bf16* As_h = (bf16*)(smem + F_AH);
    float* v_s[2] = { (float*)(smem + F_V), (float*)(smem + F_V) + 64 * 72 };
    float* scr1 = (float*)(smem + F_B);              // endpoint scratch (inside B region)
    float* scr2 = scr1 + 8192;

    const int tid = threadIdx.x, wid = tid >> 5, lane = tid & 31;
    const int wy = wid >> 2, wx = wid & 3;           // 32-row tile, 64-col tile (one r)
    const int b0 = blockIdx.x * 64;

    auto load_B = [&](int gi) {
        const int tt = gi >> 4, nb = gi & 15;
        const int cb = nb * 256;
        const bf16* HBh = g_HBh + (size_t)tt * ENCD * 4096;
        bf16* Bh = (bf16*)(smem + F_B + (uint32_t)(gi & 1) * B_STG_B);
        #pragma unroll
        for (int q = 0; q < 16; q++) {
            int i = tid + q * 256;
            int e = i >> 5, sl = (i & 31) * 8;
            cp16(smem_u32(Bh + e * CBPF + sl), HBh + (size_t)e * 4096 + cb + sl);
        }
        CP_COMMIT();
    };
    auto load_A = [&](int plane) {
        const bf16* Eh = g_ench + (size_t)plane * Bsz * ENCD;
        #pragma unroll
        for (int k = 0; k < 4; k++) {
            int i = tid + k * 256;
            int r = i >> 4, sl = (i & 15) * 8;
            *(uint4*)(As_h + r * CAPF + sl) = *(const uint4*)(Eh + (size_t)(b0 + r) * ENCD + sl);
        }
    };

    // ======== v0 (fp32 SIMT, exact enc = hi+lo) ========
    for (int i = tid; i < ENCD * Rr; i += 256) scr1[i] = Hf[i];   // [e*64+r]
    for (int i = tid; i < 64 * ENCD; i += 256) {
        int r = i >> 7, e = i & 127;
        size_t a = (size_t)(b0 + r) * ENCD + e;
        scr2[r * 128 + e] = __bfloat162float(g_ench[a]) + __bfloat162float(g_encl[a]);
    }
    __syncthreads();
    {
        const int r = tid & 63, q = tid >> 6;
        #pragma unroll
        for (int rr = 0; rr < 16; rr++) {
            int row = q * 16 + rr;
            float acc = 0.f;
            #pragma unroll 8
            for (int e = 0; e < ENCD; e++) acc += scr2[row * 128 + e] * scr1[e * 64 + r];
            v_s[0][row * 72 + r] = acc;
        }
    }
    __syncthreads();   // scratch free

    // ======== pipeline prologue ========
    load_A(1);
    load_B(0);
    int cur = 0;

    float d[2][8][4];
    #pragma unroll
    for (int rf = 0; rf < 2; rf++)
        #pragma unroll
        for (int j = 0; j < 8; j++)
            #pragma unroll
            for (int q = 0; q < 4; q++) d[rf][j][q] = 0.f;

    uint32_t ahf[8][2][4];            // hoisted A fragments, per step

    const int a_row = (lane & 15);
    const int a_kof = (lane >> 4) << 3;
    const int b_row = (lane & 7) + ((lane >> 3) & 1) * 8;
    const int b_nof = (lane >> 4) << 3;

    for (int t = 0; t < Tn - 2; t++) {
        if (t > 0) {
            __syncthreads();           // step t-1 compute + v writes complete
            load_A(t + 1);
            __syncthreads();
        }
        for (int g = 0; g < 16; g++) {
            const int gi = t * 16 + g;
            CP_WAIT(0);
            __syncthreads();                       // stage gi ready; stage gi-1 consumed
            if (gi + 1 < 160) load_B(gi + 1);

            if (g == 0) {
                // hoist A fragments for this step (A constant across 16 chunks)
                #pragma unroll
                for (int kk = 0; kk < 8; kk++)
                    #pragma unroll
                    for (int rf = 0; rf < 2; rf++) {
                        int arow = wy * 32 + rf * 16 + a_row;
                        ldmx4(ahf[kk][rf], smem_u32(As_h + arow * CAPF + kk * 16 + a_kof));
                    }
            }

            bf16* Bh = (bf16*)(smem + F_B + (uint32_t)(gi & 1) * B_STG_B);

            #pragma unroll
            for (int kk = 0; kk < 8; kk++) {
                #pragma unroll
                for (int jj = 0; jj < 4; jj++) {
                    int brow = kk * 16 + b_row;
                    int bcol = wx * 64 + jj * 16 + b_nof;
                    uint32_t bh[4];
                    ldmx4t(bh, smem_u32(Bh + brow * CBPF + bcol));
                    #pragma unroll
                    for (int s2 = 0; s2 < 2; s2++) {
                        const int j = jj * 2 + s2;
                        #pragma unroll
                        for (int rf = 0; rf < 2; rf++)
                            mma16816(d[rf][j], ahf[kk][rf], bh + s2 * 2);
                    }
                }
            }

            // register epilogue: v_new[row, r] = sum_p D[row, p] * v[row, p]
            {
                const int r_loc = g * 4 + wx;
                float* vcur = v_s[cur];
                float* vnxt = v_s[cur ^ 1];
                #pragma unroll
                for (int rf = 0; rf < 2; rf++) {
                    const int row0 = wy * 32 + rf * 16 + (lane >> 2);
                    float p0 = 0.f, p1 = 0.f;
                    #pragma unroll
                    for (int j = 0; j < 8; j++) {
                        const int p = j * 8 + (lane & 3) * 2;
                        float2 va = *(float2*)&vcur[row0 * 72 + p];
                        float2 vb = *(float2*)&vcur[(row0 + 8) * 72 + p];
                        p0 += d[rf][j][0] * va.x + d[rf][j][1] * va.y;
                        p1 += d[rf][j][2] * vb.x + d[rf][j][3] * vb.y;
                        d[rf][j][0] = 0.f; d[rf][j][1] = 0.f;
                        d[rf][j][2] = 0.f; d[rf][j][3] = 0.f;
                    }
                    p0 += __shfl_xor_sync(0xffffffffu, p0, 1);
                    p0 += __shfl_xor_sync(0xffffffffu, p0, 2);
                    p1 += __shfl_xor_sync(0xffffffffu, p1, 1);
                    p1 += __shfl_xor_sync(0xffffffffu, p1, 2);
                    if ((lane & 3) == 0) {
                        vnxt[row0 * 72 + r_loc] = p0;
                        vnxt[(row0 + 8) * 72 + r_loc] = p1;
                    }
                }
            }
        }
        cur ^= 1;
    }

    // ======== final: out[b] = sum_p v[b,p] * (sum_e enc11[b,e] * Hl[p,e]) ========
    __syncthreads();           // pipeline drained; B region free
    for (int i = tid; i < ENCD * Rr; i += 256) {
        int e = i >> 6, p = i & 63;
        scr1[i] = Hl[p * ENCD + e];                 // transposed [e*64+p]
    }
    {
        const bf16* Eh = g_ench + (size_t)(Tn - 1) * Bsz * ENCD;
        const bf16* El = g_encl + (size_t)(Tn - 1) * Bsz * ENCD;
        for (int i = tid; i < 64 * ENCD; i += 256) {
            int r = i >> 7, e = i & 127;
            size_t a = (size_t)(b0 + r) * ENCD + e;
            scr2[r * 128 + e] = __bfloat162float(Eh[a]) + __bfloat162float(El[a]);
        }
    }
    __syncthreads();
    {
        float* red = scr1 + 8192 + 8192;            // 256 floats, inside B region
        const int row = tid >> 2, q = tid & 3;
        float partial = 0.f;
        #pragma unroll
        for (int pp = 0; pp < 16; pp++) {
            int p = q * 16 + pp;
            float last = 0.f;
            #pragma unroll 8
            for (int e = 0; e < ENCD; e++) last += scr2[row * 128 + e] * scr1[e * 64 + p];
            partial += v_s[cur][row * 72 + p] * last;
        }
        red[row * 4 + q] = partial;
        __syncthreads();
        if (tid < 64)
            out[b0 + tid] = red[tid * 4 + 0] + red[tid * 4 + 1]
                          + red[tid * 4 + 2] + red[tid * 4 + 3];
    }
}

// ================= host launcher =================
extern "C" void kernel_launch(void* const* d_in, const int* in_sizes, int n_in,
                              void* d_out, int out_size) {
    const float* x  = (const float*)d_in[0];
    const float* W1 = (const float*)d_in[1];
    const float* b1 = (const float*)d_in[2];
    const float* W2 = (const float*)d_in[3];
    const float* b2 = (const float*)d_in[4];
    const float* Hf = (const float*)d_in[5];
    const float* Hm = (const float*)d_in[6];
    const float* Hl = (const float*)d_in[7];
    float* out = (float*)d_out;

    cudaFuncSetAttribute(encoder2_kernel,  cudaFuncAttributeMaxDynamicSharedMemorySize, ENC2_SMEM);
    cudaFuncSetAttribute(chain_mma_kernel, cudaFuncAttributeMaxDynamicSharedMemorySize, CHF_SMEM);

    prep_w_kernel<<<96, 256>>>(W1, W2);
    prep_hb_kernel<<<(Tn - 2) * ENCD, 256>>>(Hm);
    encoder2_kernel<<<(Bsz * Tn) / 64, 256, ENC2_SMEM>>>(x, b1, b2);
    chain_mma_kernel<<<128, 256, CHF_SMEM>>>(Hf, Hl, out);
}

// round 15
// speedup vs baseline: 4.1185x; 1.0098x over previous
#include <cuda_runtime.h>
#include <cuda_bf16.h>
#include <mma.h>
#include <cstdint>

using namespace nvcuda;
typedef __nv_bfloat16 bf16;

#define Bsz 8192
#define Tn  12
#define DIN 64
#define HID 512
#define ENCD 128
#define Rr  64

// ================= device-global scratch =================
__device__ __align__(256) bf16  g_ench[Tn * Bsz * ENCD];   // [t][b][e] hi
__device__ __align__(256) bf16  g_encl[Tn * Bsz * ENCD];   // lo (exact v0/final only)
__device__ __align__(256) bf16  g_W1hi[HID * DIN];
__device__ __align__(256) bf16  g_W2hi[ENCD * HID];
// H_mid as GEMM-B (hi only): [t][e][n = r*64+p]
__device__ __align__(256) bf16  g_HBh[(Tn - 2) * ENCD * Rr * Rr];

__device__ __forceinline__ uint32_t smem_u32(const void* p) {
    uint32_t a;
    asm("{ .reg .u64 t; cvta.to.shared.u64 t, %1; cvt.u32.u64 %0, t; }" : "=r"(a) : "l"(p));
    return a;
}
__device__ __forceinline__ void cp16(uint32_t dst, const void* src) {
    asm volatile("cp.async.cg.shared.global [%0], [%1], 16;" :: "r"(dst), "l"(src));
}
#define CP_COMMIT()  asm volatile("cp.async.commit_group;")
#define CP_WAIT(N)   asm volatile("cp.async.wait_group %0;" :: "n"(N))

// ---- raw MMA primitives ----
__device__ __forceinline__ void ldmx4(uint32_t* r, uint32_t a) {
    asm volatile("ldmatrix.sync.aligned.m8n8.x4.shared.b16 {%0,%1,%2,%3}, [%4];"
                 : "=r"(r[0]), "=r"(r[1]), "=r"(r[2]), "=r"(r[3]) : "r"(a));
}
__device__ __forceinline__ void ldmx4t(uint32_t* r, uint32_t a) {
    asm volatile("ldmatrix.sync.aligned.m8n8.x4.trans.shared.b16 {%0,%1,%2,%3}, [%4];"
                 : "=r"(r[0]), "=r"(r[1]), "=r"(r[2]), "=r"(r[3]) : "r"(a));
}
__device__ __forceinline__ void mma16816(float* d, const uint32_t* a, const uint32_t* b) {
    asm volatile("mma.sync.aligned.m16n8k16.row.col.f32.bf16.bf16.f32 "
                 "{%0,%1,%2,%3}, {%4,%5,%6,%7}, {%8,%9}, {%0,%1,%2,%3};"
                 : "+f"(d[0]), "+f"(d[1]), "+f"(d[2]), "+f"(d[3])
                 : "r"(a[0]), "r"(a[1]), "r"(a[2]), "r"(a[3]), "r"(b[0]), "r"(b[1]));
}

// ================= prep: W hi =================
__global__ void prep_w_kernel(const float* __restrict__ W1,
                              const float* __restrict__ W2) {
    const int n1 = HID * DIN, n2 = ENCD * HID;
    for (int i = blockIdx.x * blockDim.x + threadIdx.x; i < n1 + n2;
         i += gridDim.x * blockDim.x) {
        if (i < n1) g_W1hi[i] = __float2bfloat16(W1[i]);
        else        g_W2hi[i - n1] = __float2bfloat16(W2[i - n1]);
    }
}

// ================= prep: Hm[t,p,e,r] -> HB[t][e][r*64+p] (hi only) =================
__global__ __launch_bounds__(256) void prep_hb_kernel(const float* __restrict__ Hm) {
    __shared__ float tile[64][65];              // [p][r]
    const int t = blockIdx.x >> 7;
    const int e = blockIdx.x & 127;
    const int tid = threadIdx.x;
    for (int i = tid; i < 64 * 64; i += 256) {
        int p = i >> 6, r = i & 63;
        tile[p][r] = Hm[(((size_t)(t * 64 + p) * 128) + e) * 64 + r];
    }
    __syncthreads();
    bf16* dh = g_HBh + (size_t)(t * 128 + e) * 4096;
    for (int c = tid; c < 4096; c += 256) {
        int r = c >> 6, p = c & 63;
        dh[c] = __float2bfloat16(tile[p][r]);
    }
}

// ================= encoder (256 threads, single-term hi x hi) =================
#define EX_H 0u
#define EH_H (EX_H + 64u * 72u * 2u)               // 9216
#define E_ST (EH_H + 64u * 520u * 2u)              // 75776
#define ENC2_SMEM (E_ST + 8u * 320u * 4u)          // 86016

__global__ __launch_bounds__(256, 1) void encoder2_kernel(const float* __restrict__ x,
                                                          const float* __restrict__ b1,
                                                          const float* __restrict__ b2) {
    extern __shared__ char smem[];
    bf16* xs_hi = (bf16*)(smem + EX_H);
    bf16* hs_hi = (bf16*)(smem + EH_H);
    float* stg_base = (float*)(smem + E_ST);

    const int tid = threadIdx.x, w = tid >> 5, lane = tid & 31;
    const int wy = w >> 2, wx = w & 3;
    const int n0 = blockIdx.x * 64;
    float* stg = stg_base + w * 320;
    const int frow = lane >> 1, fcol = (lane & 1) * 8;

    #pragma unroll
    for (int k = 0; k < 16; k++) {
        int idx = tid + k * 256;
        int r = idx >> 6, c = idx & 63;
        xs_hi[r * 72 + c] = __float2bfloat16(x[(size_t)(n0 + r) * DIN + c]);
    }
    __syncthreads();

    #pragma unroll
    for (int pass = 0; pass < 2; pass++) {
        const int cb = wx * 128 + pass * 64;
        wmma::fragment<wmma::accumulator, 16, 16, 16, float> acc[2][4];
        #pragma unroll
        for (int rf = 0; rf < 2; rf++)
            #pragma unroll
            for (int j = 0; j < 4; j++) wmma::fill_fragment(acc[rf][j], 0.0f);
        #pragma unroll
        for (int kk = 0; kk < 4; kk++) {
            wmma::fragment<wmma::matrix_a, 16, 16, 16, bf16, wmma::row_major> ahi[2];
            #pragma unroll
            for (int rf = 0; rf < 2; rf++)
                wmma::load_matrix_sync(ahi[rf], xs_hi + (wy * 32 + rf * 16) * 72 + kk * 16, 72);
            #pragma unroll
            for (int j = 0; j < 4; j++) {
                wmma::fragment<wmma::matrix_b, 16, 16, 16, bf16, wmma::col_major> bhi;
                wmma::load_matrix_sync(bhi, g_W1hi + (cb + j * 16) * DIN + kk * 16, DIN);
                #pragma unroll
                for (int rf = 0; rf < 2; rf++)
                    wmma::mma_sync(acc[rf][j], ahi[rf], bhi, acc[rf][j]);
            }
        }
        #pragma unroll
        for (int rf = 0; rf < 2; rf++)
            #pragma unroll
            for (int j = 0; j < 4; j++) {
                wmma::store_matrix_sync(stg, acc[rf][j], 20, wmma::mem_row_major);
                __syncwarp();
                const int rbase = wy * 32 + rf * 16 + frow;
                #pragma unroll
                for (int cc = 0; cc < 8; cc++) {
                    int gc = cb + j * 16 + fcol + cc;
                    float v = fmaxf(stg[frow * 20 + fcol + cc] + b1[gc], 0.0f);
                    hs_hi[rbase * 520 + gc] = __float2bfloat16(v);
                }
                __syncwarp();
            }
    }
    __syncthreads();

    {
        wmma::fragment<wmma::accumulator, 16, 16, 16, float> acc[2][2];
        #pragma unroll
        for (int rf = 0; rf < 2; rf++)
            #pragma unroll
            for (int j = 0; j < 2; j++) wmma::fill_fragment(acc[rf][j], 0.0f);
        #pragma unroll 8
        for (int kk = 0; kk < 32; kk++) {
            wmma::fragment<wmma::matrix_a, 16, 16, 16, bf16, wmma::row_major> ahi[2];
            #pragma unroll
            for (int rf = 0; rf < 2; rf++)
                wmma::load_matrix_sync(ahi[rf], hs_hi + (wy * 32 + rf * 16) * 520 + kk * 16, 520);
            #pragma unroll
            for (int j = 0; j < 2; j++) {
                wmma::fragment<wmma::matrix_b, 16, 16, 16, bf16, wmma::col_major> bhi;
                wmma::load_matrix_sync(bhi, g_W2hi + (wx * 32 + j * 16) * HID + kk * 16, HID);
                #pragma unroll
                for (int rf = 0; rf < 2; rf++)
                    wmma::mma_sync(acc[rf][j], ahi[rf], bhi, acc[rf][j]);
            }
        }
        #pragma unroll
        for (int rf = 0; rf < 2; rf++)
            #pragma unroll
            for (int j = 0; j < 2; j++) {
                wmma::store_matrix_sync(stg, acc[rf][j], 20, wmma::mem_row_major);
                __syncwarp();
                const int n = n0 + wy * 32 + rf * 16 + frow;
                const int b = n / Tn, tt = n % Tn;
                #pragma unroll
                for (int cc = 0; cc < 8; cc++) {
                    int e = wx * 32 + j * 16 + fcol + cc;
                    float v = fmaxf(stg[frow * 20 + fcol + cc] + b2[e], 0.0f);
                    bf16 hi = __float2bfloat16(v);
                    g_ench[(size_t)(tt * Bsz + b) * ENCD + e] = hi;
                    g_encl[(size_t)(tt * Bsz + b) * ENCD + e] = __float2bfloat16(v - __bfloat162float(hi));
                }
                __syncwarp();
            }
    }
}

// ================= fused chain: single-term bf16, reg-double-buffered B frags =================
#define CAPF 136
#define CBPF 264
#define F_AH 0u
#define F_V  (F_AH + 64u * CAPF * 2u)               // 17408
#define F_B  (F_V + 2u * 64u * 72u * 4u)            // 54272
#define B_STG_B (128u * CBPF * 2u)                  // 67584 per stage
#define CHF_SMEM (F_B + 2u * B_STG_B)               // 189440 B

__global__ __launch_bounds__(256, 1) void chain_mma_kernel(const float* __restrict__ Hf,
                                                           const float* __restrict__ Hl,
                                                           float* __restrict__ out) {
    extern __shared__ char smem[];
    bf16* As_h = (bf16*)(smem + F_AH);
    float* v_s[2] = { (float*)(smem + F_V), (float*)(smem + F_V) + 64 * 72 };
    float* scr1 = (float*)(smem + F_B);              // endpoint scratch (inside B region)
    float* scr2 = scr1 + 8192;

    const int tid = threadIdx.x, wid = tid >> 5, lane = tid & 31;
    const int wy = wid >> 2, wx = wid & 3;           // 32-row tile, 64-col tile (one r)
    const int b0 = blockIdx.x * 64;

    auto load_B = [&](int gi) {
        const int tt = gi >> 4, nb = gi & 15;
        const int cb = nb * 256;
        const bf16* HBh = g_HBh + (size_t)tt * ENCD * 4096;
        bf16* Bh = (bf16*)(smem + F_B + (uint32_t)(gi & 1) * B_STG_B);
        #pragma unroll
        for (int q = 0; q < 16; q++) {
            int i = tid + q * 256;
            int e = i >> 5, sl = (i & 31) * 8;
            cp16(smem_u32(Bh + e * CBPF + sl), HBh + (size_t)e * 4096 + cb + sl);
        }
        CP_COMMIT();
    };
    auto load_A = [&](int plane) {
        const bf16* Eh = g_ench + (size_t)plane * Bsz * ENCD;
        #pragma unroll
        for (int k = 0; k < 4; k++) {
            int i = tid + k * 256;
            int r = i >> 4, sl = (i & 15) * 8;
            *(uint4*)(As_h + r * CAPF + sl) = *(const uint4*)(Eh + (size_t)(b0 + r) * ENCD + sl);
        }
    };

    // ======== v0 (fp32 SIMT, exact enc = hi+lo) ========
    for (int i = tid; i < ENCD * Rr; i += 256) scr1[i] = Hf[i];   // [e*64+r]
    for (int i = tid; i < 64 * ENCD; i += 256) {
        int r = i >> 7, e = i & 127;
        size_t a = (size_t)(b0 + r) * ENCD + e;
        scr2[r * 128 + e] = __bfloat162float(g_ench[a]) + __bfloat162float(g_encl[a]);
    }
    __syncthreads();
    {
        const int r = tid & 63, q = tid >> 6;
        #pragma unroll
        for (int rr = 0; rr < 16; rr++) {
            int row = q * 16 + rr;
            float acc = 0.f;
            #pragma unroll 8
            for (int e = 0; e < ENCD; e++) acc += scr2[row * 128 + e] * scr1[e * 64 + r];
            v_s[0][row * 72 + r] = acc;
        }
    }
    __syncthreads();   // scratch free

    // ======== pipeline prologue ========
    load_A(1);
    load_B(0);
    int cur = 0;

    float d[2][8][4];
    #pragma unroll
    for (int rf = 0; rf < 2; rf++)
        #pragma unroll
        for (int j = 0; j < 8; j++)
            #pragma unroll
            for (int q = 0; q < 4; q++) d[rf][j][q] = 0.f;

    uint32_t ahf[8][2][4];            // hoisted A fragments, per step

    const int a_row = (lane & 15);
    const int a_kof = (lane >> 4) << 3;
    const int b_row = (lane & 7) + ((lane >> 3) & 1) * 8;
    const int b_nof = (lane >> 4) << 3;

    for (int t = 0; t < Tn - 2; t++) {
        if (t > 0) {
            __syncthreads();           // step t-1 compute + v writes complete
            load_A(t + 1);
            __syncthreads();
        }
        for (int g = 0; g < 16; g++) {
            const int gi = t * 16 + g;
            CP_WAIT(0);
            __syncthreads();                       // stage gi ready; stage gi-1 consumed
            if (gi + 1 < 160) load_B(gi + 1);

            if (g == 0) {
                // hoist A fragments for this step (A constant across 16 chunks)
                #pragma unroll
                for (int kk = 0; kk < 8; kk++)
                    #pragma unroll
                    for (int rf = 0; rf < 2; rf++) {
                        int arow = wy * 32 + rf * 16 + a_row;
                        ldmx4(ahf[kk][rf], smem_u32(As_h + arow * CAPF + kk * 16 + a_kof));
                    }
            }

            bf16* Bh = (bf16*)(smem + F_B + (uint32_t)(gi & 1) * B_STG_B);
            const uint32_t bbase = smem_u32(Bh) + (uint32_t)(wx * 64 + b_nof) * 2u
                                 + (uint32_t)b_row * (CBPF * 2u);

            // register double-buffer of B fragments: batch 4 LDSMs per kk,
            // prefetch kk+1 while issuing MMAs of kk
            uint32_t bfr[2][4][4];
            #pragma unroll
            for (int jj = 0; jj < 4; jj++)
                ldmx4t(bfr[0][jj], bbase + (uint32_t)(jj * 16) * 2u);
            #pragma unroll
            for (int kk = 0; kk < 8; kk++) {
                const int cbu = kk & 1, nbu = cbu ^ 1;
                if (kk < 7) {
                    #pragma unroll
                    for (int jj = 0; jj < 4; jj++)
                        ldmx4t(bfr[nbu][jj],
                               bbase + (uint32_t)((kk + 1) * 16) * (CBPF * 2u)
                                     + (uint32_t)(jj * 16) * 2u);
                }
                #pragma unroll
                for (int jj = 0; jj < 4; jj++)
                    #pragma unroll
                    for (int s2 = 0; s2 < 2; s2++) {
                        const int j = jj * 2 + s2;
                        #pragma unroll
                        for (int rf = 0; rf < 2; rf++)
                            mma16816(d[rf][j], ahf[kk][rf], bfr[cbu][jj] + s2 * 2);
                    }
            }

            // register epilogue: v_new[row, r] = sum_p D[row, p] * v[row, p]
            {
                const int r_loc = g * 4 + wx;
                float* vcur = v_s[cur];
                float* vnxt = v_s[cur ^ 1];
                #pragma unroll
                for (int rf = 0; rf < 2; rf++) {
                    const int row0 = wy * 32 + rf * 16 + (lane >> 2);
                    float p0 = 0.f, p1 = 0.f;
                    #pragma unroll
                    for (int j = 0; j < 8; j++) {
                        const int p = j * 8 + (lane & 3) * 2;
                        float2 va = *(float2*)&vcur[row0 * 72 + p];
                        float2 vb = *(float2*)&vcur[(row0 + 8) * 72 + p];
                        p0 += d[rf][j][0] * va.x + d[rf][j][1] * va.y;
                        p1 += d[rf][j][2] * vb.x + d[rf][j][3] * vb.y;
                        d[rf][j][0] = 0.f; d[rf][j][1] = 0.f;
                        d[rf][j][2] = 0.f; d[rf][j][3] = 0.f;
                    }
                    p0 += __shfl_xor_sync(0xffffffffu, p0, 1);
                    p0 += __shfl_xor_sync(0xffffffffu, p0, 2);
                    p1 += __shfl_xor_sync(0xffffffffu, p1, 1);
                    p1 += __shfl_xor_sync(0xffffffffu, p1, 2);
                    if ((lane & 3) == 0) {
                        vnxt[row0 * 72 + r_loc] = p0;
                        vnxt[(row0 + 8) * 72 + r_loc] = p1;
                    }
                }
            }
        }
        cur ^= 1;
    }

    // ======== final: out[b] = sum_p v[b,p] * (sum_e enc11[b,e] * Hl[p,e]) ========
    __syncthreads();           // pipeline drained; B region free
    for (int i = tid; i < ENCD * Rr; i += 256) {
        int e = i >> 6, p = i & 63;
        scr1[i] = Hl[p * ENCD + e];                 // transposed [e*64+p]
    }
    {
        const bf16* Eh = g_ench + (size_t)(Tn - 1) * Bsz * ENCD;
        const bf16* El = g_encl + (size_t)(Tn - 1) * Bsz * ENCD;
        for (int i = tid; i < 64 * ENCD; i += 256) {
            int r = i >> 7, e = i & 127;
            size_t a = (size_t)(b0 + r) * ENCD + e;
            scr2[r * 128 + e] = __bfloat162float(Eh[a]) + __bfloat162float(El[a]);
        }
    }
    __syncthreads();
    {
        float* red = scr1 + 8192 + 8192;            // 256 floats, inside B region
        const int row = tid >> 2, q = tid & 3;
        float partial = 0.f;
        #pragma unroll
        for (int pp = 0; pp < 16; pp++) {
            int p = q * 16 + pp;
            float last = 0.f;
            #pragma unroll 8
            for (int e = 0; e < ENCD; e++) last += scr2[row * 128 + e] * scr1[e * 64 + p];
            partial += v_s[cur][row * 72 + p] * last;
        }
        red[row * 4 + q] = partial;
        __syncthreads();
        if (tid < 64)
            out[b0 + tid] = red[tid * 4 + 0] + red[tid * 4 + 1]
                          + red[tid * 4 + 2] + red[tid * 4 + 3];
    }
}

// ================= host launcher =================
extern "C" void kernel_launch(void* const* d_in, const int* in_sizes, int n_in,
                              void* d_out, int out_size) {
    const float* x  = (const float*)d_in[0];
    const float* W1 = (const float*)d_in[1];
    const float* b1 = (const float*)d_in[2];
    const float* W2 = (const float*)d_in[3];
    const float* b2 = (const float*)d_in[4];
    const float* Hf = (const float*)d_in[5];
    const float* Hm = (const float*)d_in[6];
    const float* Hl = (const float*)d_in[7];
    float* out = (float*)d_out;

    cudaFuncSetAttribute(encoder2_kernel,  cudaFuncAttributeMaxDynamicSharedMemorySize, ENC2_SMEM);
    cudaFuncSetAttribute(chain_mma_kernel, cudaFuncAttributeMaxDynamicSharedMemorySize, CHF_SMEM);

    prep_w_kernel<<<96, 256>>>(W1, W2);
    prep_hb_kernel<<<(Tn - 2) * ENCD, 256>>>(Hm);
    encoder2_kernel<<<(Bsz * Tn) / 64, 256, ENC2_SMEM>>>(x, b1, b2);
    chain_mma_kernel<<<128, 256, CHF_SMEM>>>(Hf, Hl, out);
}